// round 6
// baseline (speedup 1.0000x reference)
#include <cuda_runtime.h>
#include <math.h>
#include <stdint.h>

#define N_VERTS 100000
#define N_FACES 200000
#define DIM 512

// ===================== portable PTX helpers (sm_80+) =====================
__device__ __forceinline__ uint32_t smem_to_u32(const void* smem_ptr) {
    uint32_t addr;
    asm("{ .reg .u64 tmp; cvta.to.shared.u64 tmp, %1; cvt.u32.u64 %0, tmp; }"
        : "=r"(addr) : "l"(smem_ptr));
    return addr;
}

__device__ __forceinline__ void cp16(uint32_t dst, const void* src) {
    asm volatile("cp.async.cg.shared.global [%0], [%1], 16;"
                 :: "r"(dst), "l"(src) : "memory");
}

__device__ __forceinline__ void ldm_x4(uint32_t (&r)[4], uint32_t addr) {
    asm volatile("ldmatrix.sync.aligned.m8n8.x4.shared.b16 {%0,%1,%2,%3}, [%4];"
                 : "=r"(r[0]), "=r"(r[1]), "=r"(r[2]), "=r"(r[3]) : "r"(addr));
}

// s8 IMMA m16n8k32: byte-layout of fragments identical to bf16 m16n8k16
__device__ __forceinline__ void mma_s8(int (&d)[4], const uint32_t (&a)[4],
                                       uint32_t b0, uint32_t b1) {
    asm volatile(
        "mma.sync.aligned.m16n8k32.row.col.s32.s8.s8.s32 "
        "{%0,%1,%2,%3}, {%4,%5,%6,%7}, {%8,%9}, {%0,%1,%2,%3};"
        : "+r"(d[0]), "+r"(d[1]), "+r"(d[2]), "+r"(d[3])
        : "r"(a[0]), "r"(a[1]), "r"(a[2]), "r"(a[3]), "r"(b0), "r"(b1));
}

__device__ __forceinline__ uint32_t pack4(int a, int b, int c, int d) {
    return (uint32_t)(a & 0xFF) | ((uint32_t)(b & 0xFF) << 8) |
           ((uint32_t)(c & 0xFF) << 16) | ((uint32_t)(d & 0xFF) << 24);
}

// quantize x -> (hi, lo) with q = round(x*inv), q in [-16256,16256]
__device__ __forceinline__ void quant2(float x, float inv, int& hi, int& lo) {
    int qi = __float2int_rn(x * inv);
    hi = (qi + 64) >> 7;
    lo = qi - (hi << 7);
}

// ===================== scratch (no allocations allowed) =====================
__device__ int8_t g_xh[(size_t)N_FACES * DIM];
__device__ int8_t g_xl[(size_t)N_FACES * DIM];
__device__ int8_t g_yh[(size_t)N_FACES * DIM];
__device__ int8_t g_yl[(size_t)N_FACES * DIM];
__device__ float  g_yf[(size_t)N_FACES * DIM];   // f32 intermediate
__device__ float  g_h3[(size_t)N_FACES * 256];
__device__ float  g_out12[(size_t)N_FACES * 12];
__device__ float  g_sum[N_VERTS * 3];
__device__ float  g_cnt[N_VERTS];
__device__ float  g_sA1[N_FACES];
__device__ float  g_sA2[N_FACES];
__device__ float  g_sA3[N_FACES];
// quantized transposed weights: wq[n][k]
__device__ int8_t g_w1h[DIM * DIM];
__device__ int8_t g_w1l[DIM * DIM];
__device__ int8_t g_w2h[DIM * DIM];
__device__ int8_t g_w2l[DIM * DIM];
__device__ int8_t g_w3h[256 * DIM];
__device__ int8_t g_w3l[256 * DIM];
__device__ float  g_sW1[DIM];
__device__ float  g_sW2[DIM];
__device__ float  g_sW3[256];

// ===================== zero accumulators =====================
__global__ void zero_kernel() {
    int i = blockIdx.x * blockDim.x + threadIdx.x;
    if (i < N_VERTS * 3) g_sum[i] = 0.0f;
    if (i < N_VERTS) g_cnt[i] = 0.0f;
}

// ===================== weight transpose + quantize =====================
// W is [K=512][N] row-major; one block per output-neuron n; 128 threads.
__global__ void quant_w_kernel(const float* __restrict__ W,
                               int8_t* __restrict__ Qh, int8_t* __restrict__ Ql,
                               float* __restrict__ sW, int N) {
    __shared__ float red[4];
    __shared__ float s_inv;
    const int n = blockIdx.x;
    const int t = threadIdx.x;
    float w[4];
    float m = 0.0f;
#pragma unroll
    for (int j = 0; j < 4; j++) {
        int k = t + 128 * j;
        w[j] = W[(size_t)k * N + n];
        m = fmaxf(m, fabsf(w[j]));
    }
#pragma unroll
    for (int off = 16; off; off >>= 1)
        m = fmaxf(m, __shfl_xor_sync(0xffffffffu, m, off));
    if ((t & 31) == 0) red[t >> 5] = m;
    __syncthreads();
    if (t == 0) {
        float s = fmaxf(fmaxf(red[0], red[1]), fmaxf(red[2], red[3]));
        s = fmaxf(s, 1e-20f);
        sW[n] = s * (1.0f / 16256.0f);
        s_inv = 16256.0f / s;
    }
    __syncthreads();
    float inv = s_inv;
#pragma unroll
    for (int j = 0; j < 4; j++) {
        int k = t + 128 * j;
        int hi, lo;
        quant2(w[j], inv, hi, lo);
        Qh[(size_t)n * DIM + k] = (int8_t)hi;
        Ql[(size_t)n * DIM + k] = (int8_t)lo;
    }
}

// ===================== gather + mean + quantize =====================
__global__ void gather_quant_kernel(const float* __restrict__ features,
                                    const int* __restrict__ faces,
                                    int8_t* __restrict__ outH,
                                    int8_t* __restrict__ outL,
                                    float* __restrict__ sA) {
    __shared__ float red[4];
    __shared__ float s_inv;
    const int f = blockIdx.x;
    const int t = threadIdx.x;   // 128 threads x float4
    int i0 = faces[f * 3 + 0];
    int i1 = faces[f * 3 + 1];
    int i2 = faces[f * 3 + 2];
    float4 a = ((const float4*)(features + (size_t)i0 * DIM))[t];
    float4 b = ((const float4*)(features + (size_t)i1 * DIM))[t];
    float4 d = ((const float4*)(features + (size_t)i2 * DIM))[t];
    const float k3 = 1.0f / 3.0f;
    float v[4];
    v[0] = (a.x + b.x + d.x) * k3;
    v[1] = (a.y + b.y + d.y) * k3;
    v[2] = (a.z + b.z + d.z) * k3;
    v[3] = (a.w + b.w + d.w) * k3;
    float m = fmaxf(fmaxf(fabsf(v[0]), fabsf(v[1])),
                    fmaxf(fabsf(v[2]), fabsf(v[3])));
#pragma unroll
    for (int off = 16; off; off >>= 1)
        m = fmaxf(m, __shfl_xor_sync(0xffffffffu, m, off));
    if ((t & 31) == 0) red[t >> 5] = m;
    __syncthreads();
    if (t == 0) {
        float s = fmaxf(fmaxf(red[0], red[1]), fmaxf(red[2], red[3]));
        s = fmaxf(s, 1e-20f);
        sA[f] = s * (1.0f / 16256.0f);
        s_inv = 16256.0f / s;
    }
    __syncthreads();
    float inv = s_inv;
    int h[4], l[4];
#pragma unroll
    for (int j = 0; j < 4; j++) quant2(v[j], inv, h[j], l[j]);
    ((uint32_t*)(outH + (size_t)f * DIM))[t] = pack4(h[0], h[1], h[2], h[3]);
    ((uint32_t*)(outL + (size_t)f * DIM))[t] = pack4(l[0], l[1], l[2], l[3]);
}

// ===================== row quantize (f32 [M,512] -> int8 hi/lo + scale) =====
__global__ void quant_rows_kernel(const float* __restrict__ in,
                                  int8_t* __restrict__ outH,
                                  int8_t* __restrict__ outL,
                                  float* __restrict__ sA) {
    __shared__ float red[4];
    __shared__ float s_inv;
    const int f = blockIdx.x;
    const int t = threadIdx.x;   // 128
    float4 x = ((const float4*)(in + (size_t)f * DIM))[t];
    float v[4] = {x.x, x.y, x.z, x.w};
    float m = fmaxf(fmaxf(fabsf(v[0]), fabsf(v[1])),
                    fmaxf(fabsf(v[2]), fabsf(v[3])));
#pragma unroll
    for (int off = 16; off; off >>= 1)
        m = fmaxf(m, __shfl_xor_sync(0xffffffffu, m, off));
    if ((t & 31) == 0) red[t >> 5] = m;
    __syncthreads();
    if (t == 0) {
        float s = fmaxf(fmaxf(red[0], red[1]), fmaxf(red[2], red[3]));
        s = fmaxf(s, 1e-20f);
        sA[f] = s * (1.0f / 16256.0f);
        s_inv = 16256.0f / s;
    }
    __syncthreads();
    float inv = s_inv;
    int h[4], l[4];
#pragma unroll
    for (int j = 0; j < 4; j++) quant2(v[j], inv, h[j], l[j]);
    ((uint32_t*)(outH + (size_t)f * DIM))[t] = pack4(h[0], h[1], h[2], h[3]);
    ((uint32_t*)(outL + (size_t)f * DIM))[t] = pack4(l[0], l[1], l[2], l[3]);
}

// ===================== IMMA split-int8 GEMM =====================
// out[M, NT] = relu((sA.outer(sW)) * (16384*HH + 128*(HL+LH)) + bias)
// CTA tile 128x128, 512 threads (16 warps, 4x4), warp tile 32x32.
// K chunks of 64 int8 bytes (2 x k32 units), 2-stage cp.async.
#define ROW_B      80                 // 64B data + 16B pad per smem row
#define BUF_BYTES  (128 * ROW_B)      // 10240
#define STG_BYTES  (4 * BUF_BYTES)    // 40960
#define SM_TOTAL_G (2 * STG_BYTES)    // 81920

template <int NT>
__global__ void __launch_bounds__(512, 1)
gemm_imma(const int8_t* __restrict__ Ah, const int8_t* __restrict__ Al,
          const int8_t* __restrict__ Bh, const int8_t* __restrict__ Bl,
          const float* __restrict__ sAp, const float* __restrict__ sWp,
          const float* __restrict__ bias, float* __restrict__ out, int M) {
    extern __shared__ char smem[];
    const uint32_t su = smem_to_u32(smem);
    const int tid = threadIdx.x;
    const int m0 = blockIdx.y * 128;
    const int n0 = blockIdx.x * 128;

    const int lane = tid & 31;
    const int warp = tid >> 5;
    const int wm = warp & 3;    // 4 warps along M (32 rows)
    const int wn = warp >> 2;   // 4 warps along N (32 cols)

    const uint32_t aRow = wm * 32 + (lane & 15);
    const uint32_t aCol = (lane >> 4) * 16;
    const uint32_t bRow = wn * 32 + (lane & 7) + ((lane & 16) >> 1);
    const uint32_t bCol = (lane & 8) ? 16u : 0u;

    const uint32_t aHiB = su + aRow * ROW_B + aCol;                  // buf0
    const uint32_t aLoB = aHiB + BUF_BYTES;                          // buf1
    const uint32_t bHiB = su + 2 * BUF_BYTES + bRow * ROW_B + bCol;  // buf2
    const uint32_t bLoB = bHiB + BUF_BYTES;                          // buf3

    const int ldRow = tid >> 2;     // 0..127
    const int ldQ = tid & 3;        // 4 x 16B = 64B row

    int accHH[2][4][4], accD2[2][4][4];
#pragma unroll
    for (int t = 0; t < 2; t++)
#pragma unroll
        for (int j = 0; j < 4; j++)
#pragma unroll
            for (int e = 0; e < 4; e++) { accHH[t][j][e] = 0; accD2[t][j][e] = 0; }

    auto load_stage = [&](int stage, int kc) {
        const int k0 = kc * 64;
        const uint32_t sb = (uint32_t)stage * STG_BYTES;
#pragma unroll
        for (int i = 0; i < 4; i++) {
            const uint32_t dst = su + sb + i * BUF_BYTES + ldRow * ROW_B + ldQ * 16;
            const int8_t* srcp;
            if (i == 0) {
                int gr = m0 + ldRow; if (gr >= M) gr = M - 1;
                srcp = Ah + (size_t)gr * DIM + k0 + ldQ * 16;
            } else if (i == 1) {
                int gr = m0 + ldRow; if (gr >= M) gr = M - 1;
                srcp = Al + (size_t)gr * DIM + k0 + ldQ * 16;
            } else if (i == 2) {
                srcp = Bh + (size_t)(n0 + ldRow) * DIM + k0 + ldQ * 16;
            } else {
                srcp = Bl + (size_t)(n0 + ldRow) * DIM + k0 + ldQ * 16;
            }
            cp16(dst, srcp);
        }
        asm volatile("cp.async.commit_group;" ::: "memory");
    };

    load_stage(0, 0);
    load_stage(1, 1);

    for (int kc = 0; kc < 8; kc++) {
        if (kc == 7) {
            asm volatile("cp.async.wait_group 0;" ::: "memory");
        } else {
            asm volatile("cp.async.wait_group 1;" ::: "memory");
        }
        __syncthreads();

        const uint32_t sb = (uint32_t)(kc & 1) * STG_BYTES;
#pragma unroll
        for (int u = 0; u < 2; u++) {       // k32 units, 32B apart
            const uint32_t uoff = sb + u * 32;
            uint32_t ah[2][4], al[2][4];
            ldm_x4(ah[0], aHiB + uoff);
            ldm_x4(ah[1], aHiB + uoff + 16 * ROW_B);
            ldm_x4(al[0], aLoB + uoff);
            ldm_x4(al[1], aLoB + uoff + 16 * ROW_B);
            uint32_t bh0[4], bh1[4], bl0[4], bl1[4];
            ldm_x4(bh0, bHiB + uoff);
            ldm_x4(bh1, bHiB + uoff + 16 * ROW_B);
            ldm_x4(bl0, bLoB + uoff);
            ldm_x4(bl1, bLoB + uoff + 16 * ROW_B);
#pragma unroll
            for (int nf = 0; nf < 4; nf++) {
                const uint32_t* BH = (nf < 2) ? bh0 : bh1;
                const uint32_t* BL = (nf < 2) ? bl0 : bl1;
                const uint32_t h0 = BH[2 * (nf & 1)], h1 = BH[2 * (nf & 1) + 1];
                const uint32_t l0 = BL[2 * (nf & 1)], l1 = BL[2 * (nf & 1) + 1];
#pragma unroll
                for (int t = 0; t < 2; t++) {
                    mma_s8(accHH[t][nf], ah[t], h0, h1);
                    mma_s8(accD2[t][nf], ah[t], l0, l1);
                    mma_s8(accD2[t][nf], al[t], h0, h1);
                }
            }
        }
        __syncthreads();
        if (kc + 2 < 8) load_stage(kc & 1, kc + 2);
    }
    __syncthreads();

    // -------- epilogue: combine, stage in smem f32 [128][132] --------
    float* sout = (float*)smem;
#pragma unroll
    for (int t = 0; t < 2; t++)
#pragma unroll
        for (int nf = 0; nf < 4; nf++) {
            const int row = wm * 32 + t * 16 + (lane >> 2);
            const int col = wn * 32 + nf * 8 + (lane & 3) * 2;
            float f0 = fmaf(16384.0f, (float)accHH[t][nf][0], 128.0f * (float)accD2[t][nf][0]);
            float f1 = fmaf(16384.0f, (float)accHH[t][nf][1], 128.0f * (float)accD2[t][nf][1]);
            float f2 = fmaf(16384.0f, (float)accHH[t][nf][2], 128.0f * (float)accD2[t][nf][2]);
            float f3 = fmaf(16384.0f, (float)accHH[t][nf][3], 128.0f * (float)accD2[t][nf][3]);
            sout[row * 132 + col]           = f0;
            sout[row * 132 + col + 1]       = f1;
            sout[(row + 8) * 132 + col]     = f2;
            sout[(row + 8) * 132 + col + 1] = f3;
        }
    __syncthreads();

#pragma unroll
    for (int i = 0; i < 8; i++) {
        const int lin = tid + i * 512;    // 0..4095
        const int row = lin >> 5;
        const int q = lin & 31;
        const int gr = m0 + row;
        if (gr >= M) continue;
        float4 v = *(float4*)&sout[row * 132 + q * 4];
        const float sa = __ldg(&sAp[gr]);
        const float4 sw = __ldg((const float4*)&sWp[n0 + q * 4]);
        const float4 bb = __ldg((const float4*)&bias[n0 + q * 4]);
        v.x = fmaxf(fmaf(v.x, sa * sw.x, bb.x), 0.0f);
        v.y = fmaxf(fmaf(v.y, sa * sw.y, bb.y), 0.0f);
        v.z = fmaxf(fmaf(v.z, sa * sw.z, bb.z), 0.0f);
        v.w = fmaxf(fmaf(v.w, sa * sw.w, bb.w), 0.0f);
        *(float4*)&out[(size_t)gr * NT + n0 + q * 4] = v;
    }
}

// ===================== final tiny GEMM =====================
__global__ void gemm4_kernel(const float* __restrict__ A, const float* __restrict__ W4,
                             const float* __restrict__ b4, float* __restrict__ out12) {
    __shared__ float Ws[12][256];
    __shared__ float bs[12];
    int tid = threadIdx.x;  // 128
    for (int i = tid; i < 256 * 12; i += 128) {
        int k = i / 12, j = i % 12;
        Ws[j][k] = W4[i];
    }
    if (tid < 12) bs[tid] = b4[tid];
    __syncthreads();

    int warp = tid >> 5, lane = tid & 31;
    int row = blockIdx.x * 4 + warp;
    if (row >= N_FACES) return;
    const float* a = A + (size_t)row * 256;
    float acc[12];
#pragma unroll
    for (int j = 0; j < 12; j++) acc[j] = 0.0f;
    for (int k = lane; k < 256; k += 32) {
        float h = a[k];
#pragma unroll
        for (int j = 0; j < 12; j++) acc[j] += h * Ws[j][k];
    }
#pragma unroll
    for (int j = 0; j < 12; j++) {
#pragma unroll
        for (int off = 16; off; off >>= 1)
            acc[j] += __shfl_down_sync(0xffffffffu, acc[j], off);
    }
    if (lane == 0) {
#pragma unroll
        for (int j = 0; j < 12; j++) out12[(size_t)row * 12 + j] = acc[j] + bs[j];
    }
}

// ===================== procrustes + transform + scatter =====================
__device__ __forceinline__ void jrot(double A[3][3], double V[3][3], int p, int q) {
    double apq = A[p][q];
    if (fabs(apq) < 1e-300) return;
    double tau = (A[q][q] - A[p][p]) / (2.0 * apq);
    double t = copysign(1.0, tau) / (fabs(tau) + sqrt(1.0 + tau * tau));
    double c = 1.0 / sqrt(1.0 + t * t);
    double s = t * c;
#pragma unroll
    for (int k = 0; k < 3; k++) {
        double akp = A[k][p], akq = A[k][q];
        A[k][p] = c * akp - s * akq;
        A[k][q] = s * akp + c * akq;
    }
#pragma unroll
    for (int k = 0; k < 3; k++) {
        double apk = A[p][k], aqk = A[q][k];
        A[p][k] = c * apk - s * aqk;
        A[q][k] = s * apk + c * aqk;
    }
#pragma unroll
    for (int k = 0; k < 3; k++) {
        double vkp = V[k][p], vkq = V[k][q];
        V[k][p] = c * vkp - s * vkq;
        V[k][q] = s * vkp + c * vkq;
    }
}

__global__ void procrustes_kernel(const float* __restrict__ out12,
                                  const float* __restrict__ verts,
                                  const int* __restrict__ faces,
                                  float* __restrict__ out_trans,
                                  float* __restrict__ out_rot) {
    int f = blockIdx.x * blockDim.x + threadIdx.x;
    if (f >= N_FACES) return;

    double Mm[3][3];
#pragma unroll
    for (int i = 0; i < 3; i++)
#pragma unroll
        for (int j = 0; j < 3; j++)
            Mm[i][j] = (double)out12[(size_t)f * 12 + i * 3 + j];

    double A[3][3], V[3][3];
#pragma unroll
    for (int i = 0; i < 3; i++)
#pragma unroll
        for (int j = 0; j < 3; j++) {
            double s = 0.0;
#pragma unroll
            for (int k = 0; k < 3; k++) s += Mm[k][i] * Mm[k][j];
            A[i][j] = s;
            V[i][j] = (i == j) ? 1.0 : 0.0;
        }

#pragma unroll
    for (int sweep = 0; sweep < 8; sweep++) {
        jrot(A, V, 0, 1);
        jrot(A, V, 0, 2);
        jrot(A, V, 1, 2);
    }

    double lam[3] = {A[0][0], A[1][1], A[2][2]};
#pragma unroll
    for (int a = 0; a < 2; a++) {
        int mx = a;
#pragma unroll
        for (int b = 0; b < 3; b++)
            if (b > a && lam[b] > lam[mx]) mx = b;
        if (mx != a) {
            double tl = lam[a]; lam[a] = lam[mx]; lam[mx] = tl;
#pragma unroll
            for (int k = 0; k < 3; k++) {
                double tv = V[k][a]; V[k][a] = V[k][mx]; V[k][mx] = tv;
            }
        }
    }

    double Bc[3][3];
#pragma unroll
    for (int i = 0; i < 3; i++)
#pragma unroll
        for (int k = 0; k < 3; k++) {
            double s = 0.0;
#pragma unroll
            for (int j = 0; j < 3; j++) s += Mm[i][j] * V[j][k];
            Bc[i][k] = s;
        }

    double u1[3], u2[3], u3[3];
    double n1 = sqrt(Bc[0][0] * Bc[0][0] + Bc[1][0] * Bc[1][0] + Bc[2][0] * Bc[2][0]);
    double in1 = 1.0 / fmax(n1, 1e-150);
#pragma unroll
    for (int i = 0; i < 3; i++) u1[i] = Bc[i][0] * in1;
    double d12 = u1[0] * Bc[0][1] + u1[1] * Bc[1][1] + u1[2] * Bc[2][1];
    double w[3];
#pragma unroll
    for (int i = 0; i < 3; i++) w[i] = Bc[i][1] - d12 * u1[i];
    double n2 = sqrt(w[0] * w[0] + w[1] * w[1] + w[2] * w[2]);
    double in2 = 1.0 / fmax(n2, 1e-150);
#pragma unroll
    for (int i = 0; i < 3; i++) u2[i] = w[i] * in2;
    u3[0] = u1[1] * u2[2] - u1[2] * u2[1];
    u3[1] = u1[2] * u2[0] - u1[0] * u2[2];
    u3[2] = u1[0] * u2[1] - u1[1] * u2[0];

    double detV = V[0][0] * (V[1][1] * V[2][2] - V[1][2] * V[2][1])
                - V[0][1] * (V[1][0] * V[2][2] - V[1][2] * V[2][0])
                + V[0][2] * (V[1][0] * V[2][1] - V[1][1] * V[2][0]);

    float R[3][3];
#pragma unroll
    for (int i = 0; i < 3; i++)
#pragma unroll
        for (int j = 0; j < 3; j++)
            R[i][j] = (float)(u1[i] * V[j][0] + u2[i] * V[j][1] + detV * u3[i] * V[j][2]);

#pragma unroll
    for (int i = 0; i < 3; i++)
#pragma unroll
        for (int j = 0; j < 3; j++)
            out_rot[(size_t)f * 9 + i * 3 + j] = R[i][j];

    float t0 = out12[(size_t)f * 12 + 9];
    float t1 = out12[(size_t)f * 12 + 10];
    float t2 = out12[(size_t)f * 12 + 11];

#pragma unroll
    for (int c = 0; c < 3; c++) {
        int vi = faces[f * 3 + c];
        float vx = verts[(size_t)vi * 3 + 0];
        float vy = verts[(size_t)vi * 3 + 1];
        float vz = verts[(size_t)vi * 3 + 2];
        float tvx = vx * R[0][0] + vy * R[1][0] + vz * R[2][0] + t0;
        float tvy = vx * R[0][1] + vy * R[1][1] + vz * R[2][1] + t1;
        float tvz = vx * R[0][2] + vy * R[1][2] + vz * R[2][2] + t2;
        out_trans[(size_t)f * 9 + c * 3 + 0] = tvx;
        out_trans[(size_t)f * 9 + c * 3 + 1] = tvy;
        out_trans[(size_t)f * 9 + c * 3 + 2] = tvz;
        atomicAdd(&g_sum[vi * 3 + 0], tvx);
        atomicAdd(&g_sum[vi * 3 + 1], tvy);
        atomicAdd(&g_sum[vi * 3 + 2], tvz);
        atomicAdd(&g_cnt[vi], 1.0f);
    }
}

// ===================== finalize segment mean =====================
__global__ void finalize_kernel(float* __restrict__ out_vfeat) {
    int v = blockIdx.x * blockDim.x + threadIdx.x;
    if (v >= N_VERTS) return;
    float c = fmaxf(g_cnt[v], 1.0f);
    float inv = 1.0f / c;
    out_vfeat[v * 3 + 0] = g_sum[v * 3 + 0] * inv;
    out_vfeat[v * 3 + 1] = g_sum[v * 3 + 1] * inv;
    out_vfeat[v * 3 + 2] = g_sum[v * 3 + 2] * inv;
}

// ===================== launch =====================
extern "C" void kernel_launch(void* const* d_in, const int* in_sizes, int n_in,
                              void* d_out, int out_size) {
    const float* verts    = (const float*)d_in[0];
    const float* features = (const float*)d_in[1];
    const int*   faces    = (const int*)d_in[2];
    const float* W1 = (const float*)d_in[3];
    const float* b1 = (const float*)d_in[4];
    const float* W2 = (const float*)d_in[5];
    const float* b2 = (const float*)d_in[6];
    const float* W3 = (const float*)d_in[7];
    const float* b3 = (const float*)d_in[8];
    const float* W4 = (const float*)d_in[9];
    const float* b4 = (const float*)d_in[10];

    float* out = (float*)d_out;
    float* out_vfeat = out;
    float* out_trans = out + (size_t)N_VERTS * 3;
    float* out_rot   = out_trans + (size_t)N_FACES * 9;

    int8_t *p_xh, *p_xl, *p_yh, *p_yl;
    int8_t *p_w1h, *p_w1l, *p_w2h, *p_w2l, *p_w3h, *p_w3l;
    float *p_yf, *p_h3, *p_out12, *p_sA1, *p_sA2, *p_sA3, *p_sW1, *p_sW2, *p_sW3;
    cudaGetSymbolAddress((void**)&p_xh, g_xh);
    cudaGetSymbolAddress((void**)&p_xl, g_xl);
    cudaGetSymbolAddress((void**)&p_yh, g_yh);
    cudaGetSymbolAddress((void**)&p_yl, g_yl);
    cudaGetSymbolAddress((void**)&p_yf, g_yf);
    cudaGetSymbolAddress((void**)&p_h3, g_h3);
    cudaGetSymbolAddress((void**)&p_out12, g_out12);
    cudaGetSymbolAddress((void**)&p_sA1, g_sA1);
    cudaGetSymbolAddress((void**)&p_sA2, g_sA2);
    cudaGetSymbolAddress((void**)&p_sA3, g_sA3);
    cudaGetSymbolAddress((void**)&p_w1h, g_w1h);
    cudaGetSymbolAddress((void**)&p_w1l, g_w1l);
    cudaGetSymbolAddress((void**)&p_w2h, g_w2h);
    cudaGetSymbolAddress((void**)&p_w2l, g_w2l);
    cudaGetSymbolAddress((void**)&p_w3h, g_w3h);
    cudaGetSymbolAddress((void**)&p_w3l, g_w3l);
    cudaGetSymbolAddress((void**)&p_sW1, g_sW1);
    cudaGetSymbolAddress((void**)&p_sW2, g_sW2);
    cudaGetSymbolAddress((void**)&p_sW3, g_sW3);

    cudaFuncSetAttribute(gemm_imma<512>,
                         cudaFuncAttributeMaxDynamicSharedMemorySize, SM_TOTAL_G);
    cudaFuncSetAttribute(gemm_imma<256>,
                         cudaFuncAttributeMaxDynamicSharedMemorySize, SM_TOTAL_G);

    // 1. zero accumulators
    zero_kernel<<<(N_VERTS * 3 + 255) / 256, 256>>>();

    // 2. weight transpose + quantize
    quant_w_kernel<<<DIM, 128>>>(W1, p_w1h, p_w1l, p_sW1, DIM);
    quant_w_kernel<<<DIM, 128>>>(W2, p_w2h, p_w2l, p_sW2, DIM);
    quant_w_kernel<<<256, 128>>>(W3, p_w3h, p_w3l, p_sW3, 256);

    // 3. gather + mean + quantize
    gather_quant_kernel<<<N_FACES, 128>>>(features, faces, p_xh, p_xl, p_sA1);

    // 4. MLP on int8 IMMA tensor cores
    {
        dim3 blk(512);
        dim3 g12(4, (N_FACES + 127) / 128);
        gemm_imma<512><<<g12, blk, SM_TOTAL_G>>>(p_xh, p_xl, p_w1h, p_w1l,
                                                 p_sA1, p_sW1, b1, p_yf, N_FACES);
        quant_rows_kernel<<<N_FACES, 128>>>(p_yf, p_yh, p_yl, p_sA2);
        gemm_imma<512><<<g12, blk, SM_TOTAL_G>>>(p_yh, p_yl, p_w2h, p_w2l,
                                                 p_sA2, p_sW2, b2, p_yf, N_FACES);
        quant_rows_kernel<<<N_FACES, 128>>>(p_yf, p_xh, p_xl, p_sA3);
        dim3 g3(2, (N_FACES + 127) / 128);
        gemm_imma<256><<<g3, blk, SM_TOTAL_G>>>(p_xh, p_xl, p_w3h, p_w3l,
                                                p_sA3, p_sW3, b3, p_h3, N_FACES);
        gemm4_kernel<<<(N_FACES + 3) / 4, 128>>>(p_h3, W4, b4, p_out12);
    }

    // 5. procrustes + transform + scatter
    procrustes_kernel<<<(N_FACES + 255) / 256, 256>>>(p_out12, verts, faces,
                                                      out_trans, out_rot);

    // 6. segment mean
    finalize_kernel<<<(N_VERTS + 255) / 256, 256>>>(out_vfeat);
}

// round 7
// speedup vs baseline: 2.3384x; 2.3384x over previous
#include <cuda_runtime.h>
#include <cuda_bf16.h>
#include <math.h>
#include <stdint.h>

#define N_VERTS 100000
#define N_FACES 200000
#define DIM 512

// ===================== portable PTX helpers (sm_80+) =====================
__device__ __forceinline__ uint32_t smem_to_u32(const void* smem_ptr) {
    uint32_t addr;
    asm("{ .reg .u64 tmp; cvta.to.shared.u64 tmp, %1; cvt.u32.u64 %0, tmp; }"
        : "=r"(addr) : "l"(smem_ptr));
    return addr;
}

__device__ __forceinline__ void cp16(uint32_t dst, const void* src) {
    asm volatile("cp.async.cg.shared.global [%0], [%1], 16;"
                 :: "r"(dst), "l"(src) : "memory");
}

__device__ __forceinline__ void ldm_x4(uint32_t (&r)[4], uint32_t addr) {
    asm volatile("ldmatrix.sync.aligned.m8n8.x4.shared.b16 {%0,%1,%2,%3}, [%4];"
                 : "=r"(r[0]), "=r"(r[1]), "=r"(r[2]), "=r"(r[3]) : "r"(addr));
}

__device__ __forceinline__ void mma_bf16(float (&d)[4], const uint32_t (&a)[4],
                                         uint32_t b0, uint32_t b1) {
    asm volatile(
        "mma.sync.aligned.m16n8k16.row.col.f32.bf16.bf16.f32 "
        "{%0,%1,%2,%3}, {%4,%5,%6,%7}, {%8,%9}, {%0,%1,%2,%3};"
        : "+f"(d[0]), "+f"(d[1]), "+f"(d[2]), "+f"(d[3])
        : "r"(a[0]), "r"(a[1]), "r"(a[2]), "r"(a[3]), "r"(b0), "r"(b1));
}

__device__ __forceinline__ uint32_t pack_bf16(float a, float b) {
    __nv_bfloat162 t = __floats2bfloat162_rn(a, b);
    return *(uint32_t*)&t;
}

// ===================== scratch (no allocations allowed) =====================
__device__ __nv_bfloat16 g_f_hi[(size_t)N_VERTS * DIM];   // split features
__device__ __nv_bfloat16 g_f_lo[(size_t)N_VERTS * DIM];
__device__ float         g_G[(size_t)N_VERTS * DIM];      // features @ W1
__device__ __nv_bfloat16 g_x_hi[(size_t)N_FACES * DIM];
__device__ __nv_bfloat16 g_x_lo[(size_t)N_FACES * DIM];
__device__ __nv_bfloat16 g_y_hi[(size_t)N_FACES * DIM];
__device__ __nv_bfloat16 g_y_lo[(size_t)N_FACES * DIM];
__device__ float g_h3[(size_t)N_FACES * 256];
__device__ float g_out12[(size_t)N_FACES * 12];
__device__ float g_sum[N_VERTS * 3];
__device__ float g_cnt[N_VERTS];
// transposed + split weights: Wt[n][k] = W[k][n]
__device__ __nv_bfloat16 g_w1t_hi[DIM * DIM];
__device__ __nv_bfloat16 g_w1t_lo[DIM * DIM];
__device__ __nv_bfloat16 g_w2t_hi[DIM * DIM];
__device__ __nv_bfloat16 g_w2t_lo[DIM * DIM];
__device__ __nv_bfloat16 g_w3t_hi[256 * DIM];
__device__ __nv_bfloat16 g_w3t_lo[256 * DIM];

// ===================== zero accumulators =====================
__global__ void zero_kernel() {
    int i = blockIdx.x * blockDim.x + threadIdx.x;
    if (i < N_VERTS * 3) g_sum[i] = 0.0f;
    if (i < N_VERTS) g_cnt[i] = 0.0f;
}

// ===================== weight transpose + split =====================
__global__ void convert_w_kernel(const float* __restrict__ W,
                                 __nv_bfloat16* __restrict__ Thi,
                                 __nv_bfloat16* __restrict__ Tlo,
                                 int K, int N) {
    int id = blockIdx.x * blockDim.x + threadIdx.x;
    if (id >= K * N) return;
    int k = id / N, n = id % N;
    float v = W[id];
    __nv_bfloat16 h = __float2bfloat16(v);
    float lo = v - __bfloat162float(h);
    Thi[(size_t)n * K + k] = h;
    Tlo[(size_t)n * K + k] = __float2bfloat16(lo);
}

// ===================== split f32 rows -> bf16 hi/lo =====================
__global__ void split_rows_kernel(const float* __restrict__ in,
                                  __nv_bfloat16* __restrict__ outHi,
                                  __nv_bfloat16* __restrict__ outLo) {
    int r = blockIdx.x;
    int c = threadIdx.x;  // 128 threads x float4
    float4 x = ((const float4*)(in + (size_t)r * DIM))[c];
    float v[4] = {x.x, x.y, x.z, x.w};
    uint32_t ph[2], pl[2];
#pragma unroll
    for (int p = 0; p < 2; p++) {
        __nv_bfloat16 h0 = __float2bfloat16(v[2 * p]);
        __nv_bfloat16 h1 = __float2bfloat16(v[2 * p + 1]);
        ph[p] = (uint32_t)__bfloat16_as_ushort(h0) |
                ((uint32_t)__bfloat16_as_ushort(h1) << 16);
        pl[p] = pack_bf16(v[2 * p] - __bfloat162float(h0),
                          v[2 * p + 1] - __bfloat162float(h1));
    }
    *(uint2*)(outHi + (size_t)r * DIM + c * 4) = make_uint2(ph[0], ph[1]);
    *(uint2*)(outLo + (size_t)r * DIM + c * 4) = make_uint2(pl[0], pl[1]);
}

// ===================== gather G rows + mean + bias + relu + split ==========
__global__ void gather_relu_split_kernel(const float* __restrict__ G,
                                         const int* __restrict__ faces,
                                         const float* __restrict__ b1,
                                         __nv_bfloat16* __restrict__ outHi,
                                         __nv_bfloat16* __restrict__ outLo) {
    int f = blockIdx.x;
    int c = threadIdx.x;  // 128 threads x float4
    int i0 = faces[f * 3 + 0];
    int i1 = faces[f * 3 + 1];
    int i2 = faces[f * 3 + 2];
    float4 a = ((const float4*)(G + (size_t)i0 * DIM))[c];
    float4 b = ((const float4*)(G + (size_t)i1 * DIM))[c];
    float4 d = ((const float4*)(G + (size_t)i2 * DIM))[c];
    float4 bb = __ldg((const float4*)&b1[c * 4]);
    const float k3 = 1.0f / 3.0f;
    float v[4];
    v[0] = fmaxf(fmaf(a.x + b.x + d.x, k3, bb.x), 0.0f);
    v[1] = fmaxf(fmaf(a.y + b.y + d.y, k3, bb.y), 0.0f);
    v[2] = fmaxf(fmaf(a.z + b.z + d.z, k3, bb.z), 0.0f);
    v[3] = fmaxf(fmaf(a.w + b.w + d.w, k3, bb.w), 0.0f);
    uint32_t ph[2], pl[2];
#pragma unroll
    for (int p = 0; p < 2; p++) {
        __nv_bfloat16 h0 = __float2bfloat16(v[2 * p]);
        __nv_bfloat16 h1 = __float2bfloat16(v[2 * p + 1]);
        ph[p] = (uint32_t)__bfloat16_as_ushort(h0) |
                ((uint32_t)__bfloat16_as_ushort(h1) << 16);
        pl[p] = pack_bf16(v[2 * p] - __bfloat162float(h0),
                          v[2 * p + 1] - __bfloat162float(h1));
    }
    *(uint2*)(outHi + (size_t)f * DIM + c * 4) = make_uint2(ph[0], ph[1]);
    *(uint2*)(outLo + (size_t)f * DIM + c * 4) = make_uint2(pl[0], pl[1]);
}

// ===================== HMMA split-bf16 GEMM (2-stage, 2 CTAs/SM) ===========
// OUT_MODE 0: relu+bias -> bf16 hi/lo.  1: relu+bias -> f32.  2: raw -> f32.
#define STG_BYTES   40960           // 4 * 128 * 80
#define BUF_BYTES   10240           // 128 * 80
#define ROW_B       80              // bytes per smem row
#define SM_TOTAL_G  (2 * STG_BYTES) // 81920

template <int N_TOTAL, int OUT_MODE>
__global__ void __launch_bounds__(256, 2)
gemm_hmma(const __nv_bfloat16* __restrict__ Ahi,
          const __nv_bfloat16* __restrict__ Alo,
          const __nv_bfloat16* __restrict__ Bhi,
          const __nv_bfloat16* __restrict__ Blo,
          const float* __restrict__ bias,
          void* __restrict__ outHiV, void* __restrict__ outLoV,
          int M) {
    extern __shared__ char smem[];
    const uint32_t su = smem_to_u32(smem);
    const int tid = threadIdx.x;
    const int m0 = blockIdx.y * 128;
    const int n0 = blockIdx.x * 128;

    const int lane = tid & 31;
    const int warp = tid >> 5;
    const int wm = warp & 3;   // 4 warps along M
    const int wn = warp >> 2;  // 2 warps along N

    const uint32_t aRow = wm * 32 + (lane & 15);
    const uint32_t aCol = (lane >> 4) * 16;
    const uint32_t bRow = wn * 64 + (lane & 7) + ((lane & 16) >> 1);
    const uint32_t bCol = (lane & 8) ? 16u : 0u;

    const uint32_t aHiB = su + aRow * ROW_B + aCol;
    const uint32_t aLoB = aHiB + BUF_BYTES;
    const uint32_t bHiB = su + 2 * BUF_BYTES + bRow * ROW_B + bCol;
    const uint32_t bLoB = bHiB + BUF_BYTES;

    const int ldRowHalf = tid >> 2;
    const int ldQ = tid & 3;

    float acc[2][8][4];
#pragma unroll
    for (int t = 0; t < 2; t++)
#pragma unroll
        for (int j = 0; j < 8; j++)
#pragma unroll
            for (int e = 0; e < 4; e++) acc[t][j][e] = 0.0f;

    auto load_stage = [&](int stage, int kc) {
        const int k0 = kc * 32;
        const uint32_t stageBase = (uint32_t)stage * STG_BYTES;
#pragma unroll
        for (int i = 0; i < 8; i++) {
            const int buf = i >> 1;
            const int r = (i & 1) * 64 + ldRowHalf;
            const uint32_t dst = su + stageBase + buf * BUF_BYTES +
                                 r * ROW_B + ldQ * 16;
            const __nv_bfloat16* srcp;
            if (buf == 0) {
                int gr = m0 + r; if (gr >= M) gr = M - 1;
                srcp = Ahi + (size_t)gr * DIM + k0 + ldQ * 8;
            } else if (buf == 1) {
                int gr = m0 + r; if (gr >= M) gr = M - 1;
                srcp = Alo + (size_t)gr * DIM + k0 + ldQ * 8;
            } else if (buf == 2) {
                srcp = Bhi + (size_t)(n0 + r) * DIM + k0 + ldQ * 8;
            } else {
                srcp = Blo + (size_t)(n0 + r) * DIM + k0 + ldQ * 8;
            }
            cp16(dst, srcp);
        }
        asm volatile("cp.async.commit_group;" ::: "memory");
    };

    load_stage(0, 0);
    load_stage(1, 1);

    for (int kc = 0; kc < 16; kc++) {
        if (kc == 15) {
            asm volatile("cp.async.wait_group 0;" ::: "memory");
        } else {
            asm volatile("cp.async.wait_group 1;" ::: "memory");
        }
        __syncthreads();

        const uint32_t sb = (uint32_t)(kc & 1) * STG_BYTES;
#pragma unroll
        for (int h = 0; h < 2; h++) {
            const uint32_t hoff = sb + h * 32;
            uint32_t ah[2][4], al[2][4];
            ldm_x4(ah[0], aHiB + hoff);
            ldm_x4(ah[1], aHiB + hoff + 16 * ROW_B);
            ldm_x4(al[0], aLoB + hoff);
            ldm_x4(al[1], aLoB + hoff + 16 * ROW_B);
#pragma unroll
            for (int p = 0; p < 4; p++) {
                uint32_t bh[4], bl[4];
                ldm_x4(bh, bHiB + hoff + p * (16 * ROW_B));
                ldm_x4(bl, bLoB + hoff + p * (16 * ROW_B));
#pragma unroll
                for (int t = 0; t < 2; t++) {
                    mma_bf16(acc[t][2 * p],     ah[t], bh[0], bh[1]);
                    mma_bf16(acc[t][2 * p + 1], ah[t], bh[2], bh[3]);
                    mma_bf16(acc[t][2 * p],     ah[t], bl[0], bl[1]);
                    mma_bf16(acc[t][2 * p + 1], ah[t], bl[2], bl[3]);
                    mma_bf16(acc[t][2 * p],     al[t], bh[0], bh[1]);
                    mma_bf16(acc[t][2 * p + 1], al[t], bh[2], bh[3]);
                }
            }
        }
        __syncthreads();
        if (kc + 2 < 16) load_stage(kc & 1, kc + 2);
    }

    // -------- epilogue --------
    float* sout = (float*)smem;
#pragma unroll
    for (int t = 0; t < 2; t++)
#pragma unroll
        for (int j = 0; j < 8; j++) {
            const int row = wm * 32 + t * 16 + (lane >> 2);
            const int col = wn * 64 + j * 8 + (lane & 3) * 2;
            sout[row * 132 + col]           = acc[t][j][0];
            sout[row * 132 + col + 1]       = acc[t][j][1];
            sout[(row + 8) * 132 + col]     = acc[t][j][2];
            sout[(row + 8) * 132 + col + 1] = acc[t][j][3];
        }
    __syncthreads();

#pragma unroll
    for (int i = 0; i < 16; i++) {
        const int lin = tid + i * 256;
        const int row = lin >> 5;
        const int q = lin & 31;
        const int gr = m0 + row;
        if (gr >= M) continue;
        float4 v = *(float4*)&sout[row * 132 + q * 4];
        if (OUT_MODE != 2) {
            const float4 bb = __ldg((const float4*)&bias[n0 + q * 4]);
            v.x = fmaxf(v.x + bb.x, 0.0f);
            v.y = fmaxf(v.y + bb.y, 0.0f);
            v.z = fmaxf(v.z + bb.z, 0.0f);
            v.w = fmaxf(v.w + bb.w, 0.0f);
        }
        if (OUT_MODE == 0) {
            __nv_bfloat16 h0 = __float2bfloat16(v.x);
            __nv_bfloat16 h1 = __float2bfloat16(v.y);
            __nv_bfloat16 h2 = __float2bfloat16(v.z);
            __nv_bfloat16 h3 = __float2bfloat16(v.w);
            uint2 vh, vl;
            vh.x = (uint32_t)__bfloat16_as_ushort(h0) |
                   ((uint32_t)__bfloat16_as_ushort(h1) << 16);
            vh.y = (uint32_t)__bfloat16_as_ushort(h2) |
                   ((uint32_t)__bfloat16_as_ushort(h3) << 16);
            vl.x = pack_bf16(v.x - __bfloat162float(h0),
                             v.y - __bfloat162float(h1));
            vl.y = pack_bf16(v.z - __bfloat162float(h2),
                             v.w - __bfloat162float(h3));
            const size_t off = (size_t)gr * N_TOTAL + n0 + q * 4;
            *(uint2*)((__nv_bfloat16*)outHiV + off) = vh;
            *(uint2*)((__nv_bfloat16*)outLoV + off) = vl;
        } else {
            *(float4*)((float*)outHiV + (size_t)gr * N_TOTAL + n0 + q * 4) = v;
        }
    }
}

// ===================== final tiny GEMM =====================
__global__ void gemm4_kernel(const float* __restrict__ A, const float* __restrict__ W4,
                             const float* __restrict__ b4, float* __restrict__ out12) {
    __shared__ float Ws[12][256];
    __shared__ float bs[12];
    int tid = threadIdx.x;  // 128
    for (int i = tid; i < 256 * 12; i += 128) {
        int k = i / 12, j = i % 12;
        Ws[j][k] = W4[i];
    }
    if (tid < 12) bs[tid] = b4[tid];
    __syncthreads();

    int warp = tid >> 5, lane = tid & 31;
    int row = blockIdx.x * 4 + warp;
    if (row >= N_FACES) return;
    const float* a = A + (size_t)row * 256;
    float acc[12];
#pragma unroll
    for (int j = 0; j < 12; j++) acc[j] = 0.0f;
    for (int k = lane; k < 256; k += 32) {
        float h = a[k];
#pragma unroll
        for (int j = 0; j < 12; j++) acc[j] += h * Ws[j][k];
    }
#pragma unroll
    for (int j = 0; j < 12; j++) {
#pragma unroll
        for (int off = 16; off; off >>= 1)
            acc[j] += __shfl_down_sync(0xffffffffu, acc[j], off);
    }
    if (lane == 0) {
#pragma unroll
        for (int j = 0; j < 12; j++) out12[(size_t)row * 12 + j] = acc[j] + bs[j];
    }
}

// ===================== procrustes + transform + scatter =====================
__device__ __forceinline__ void jrot(double A[3][3], double V[3][3], int p, int q) {
    double apq = A[p][q];
    if (fabs(apq) < 1e-300) return;
    double tau = (A[q][q] - A[p][p]) / (2.0 * apq);
    double t = copysign(1.0, tau) / (fabs(tau) + sqrt(1.0 + tau * tau));
    double c = 1.0 / sqrt(1.0 + t * t);
    double s = t * c;
#pragma unroll
    for (int k = 0; k < 3; k++) {
        double akp = A[k][p], akq = A[k][q];
        A[k][p] = c * akp - s * akq;
        A[k][q] = s * akp + c * akq;
    }
#pragma unroll
    for (int k = 0; k < 3; k++) {
        double apk = A[p][k], aqk = A[q][k];
        A[p][k] = c * apk - s * aqk;
        A[q][k] = s * apk + c * aqk;
    }
#pragma unroll
    for (int k = 0; k < 3; k++) {
        double vkp = V[k][p], vkq = V[k][q];
        V[k][p] = c * vkp - s * vkq;
        V[k][q] = s * vkp + c * vkq;
    }
}

__global__ void procrustes_kernel(const float* __restrict__ out12,
                                  const float* __restrict__ verts,
                                  const int* __restrict__ faces,
                                  float* __restrict__ out_trans,
                                  float* __restrict__ out_rot) {
    int f = blockIdx.x * blockDim.x + threadIdx.x;
    if (f >= N_FACES) return;

    double Mm[3][3];
#pragma unroll
    for (int i = 0; i < 3; i++)
#pragma unroll
        for (int j = 0; j < 3; j++)
            Mm[i][j] = (double)out12[(size_t)f * 12 + i * 3 + j];

    double A[3][3], V[3][3];
#pragma unroll
    for (int i = 0; i < 3; i++)
#pragma unroll
        for (int j = 0; j < 3; j++) {
            double s = 0.0;
#pragma unroll
            for (int k = 0; k < 3; k++) s += Mm[k][i] * Mm[k][j];
            A[i][j] = s;
            V[i][j] = (i == j) ? 1.0 : 0.0;
        }

#pragma unroll
    for (int sweep = 0; sweep < 8; sweep++) {
        jrot(A, V, 0, 1);
        jrot(A, V, 0, 2);
        jrot(A, V, 1, 2);
    }

    double lam[3] = {A[0][0], A[1][1], A[2][2]};
#pragma unroll
    for (int a = 0; a < 2; a++) {
        int mx = a;
#pragma unroll
        for (int b = 0; b < 3; b++)
            if (b > a && lam[b] > lam[mx]) mx = b;
        if (mx != a) {
            double tl = lam[a]; lam[a] = lam[mx]; lam[mx] = tl;
#pragma unroll
            for (int k = 0; k < 3; k++) {
                double tv = V[k][a]; V[k][a] = V[k][mx]; V[k][mx] = tv;
            }
        }
    }

    double Bc[3][3];
#pragma unroll
    for (int i = 0; i < 3; i++)
#pragma unroll
        for (int k = 0; k < 3; k++) {
            double s = 0.0;
#pragma unroll
            for (int j = 0; j < 3; j++) s += Mm[i][j] * V[j][k];
            Bc[i][k] = s;
        }

    double u1[3], u2[3], u3[3];
    double n1 = sqrt(Bc[0][0] * Bc[0][0] + Bc[1][0] * Bc[1][0] + Bc[2][0] * Bc[2][0]);
    double in1 = 1.0 / fmax(n1, 1e-150);
#pragma unroll
    for (int i = 0; i < 3; i++) u1[i] = Bc[i][0] * in1;
    double d12 = u1[0] * Bc[0][1] + u1[1] * Bc[1][1] + u1[2] * Bc[2][1];
    double w[3];
#pragma unroll
    for (int i = 0; i < 3; i++) w[i] = Bc[i][1] - d12 * u1[i];
    double n2 = sqrt(w[0] * w[0] + w[1] * w[1] + w[2] * w[2]);
    double in2 = 1.0 / fmax(n2, 1e-150);
#pragma unroll
    for (int i = 0; i < 3; i++) u2[i] = w[i] * in2;
    u3[0] = u1[1] * u2[2] - u1[2] * u2[1];
    u3[1] = u1[2] * u2[0] - u1[0] * u2[2];
    u3[2] = u1[0] * u2[1] - u1[1] * u2[0];

    double detV = V[0][0] * (V[1][1] * V[2][2] - V[1][2] * V[2][1])
                - V[0][1] * (V[1][0] * V[2][2] - V[1][2] * V[2][0])
                + V[0][2] * (V[1][0] * V[2][1] - V[1][1] * V[2][0]);

    float R[3][3];
#pragma unroll
    for (int i = 0; i < 3; i++)
#pragma unroll
        for (int j = 0; j < 3; j++)
            R[i][j] = (float)(u1[i] * V[j][0] + u2[i] * V[j][1] + detV * u3[i] * V[j][2]);

#pragma unroll
    for (int i = 0; i < 3; i++)
#pragma unroll
        for (int j = 0; j < 3; j++)
            out_rot[(size_t)f * 9 + i * 3 + j] = R[i][j];

    float t0 = out12[(size_t)f * 12 + 9];
    float t1 = out12[(size_t)f * 12 + 10];
    float t2 = out12[(size_t)f * 12 + 11];

#pragma unroll
    for (int c = 0; c < 3; c++) {
        int vi = faces[f * 3 + c];
        float vx = verts[(size_t)vi * 3 + 0];
        float vy = verts[(size_t)vi * 3 + 1];
        float vz = verts[(size_t)vi * 3 + 2];
        float tvx = vx * R[0][0] + vy * R[1][0] + vz * R[2][0] + t0;
        float tvy = vx * R[0][1] + vy * R[1][1] + vz * R[2][1] + t1;
        float tvz = vx * R[0][2] + vy * R[1][2] + vz * R[2][2] + t2;
        out_trans[(size_t)f * 9 + c * 3 + 0] = tvx;
        out_trans[(size_t)f * 9 + c * 3 + 1] = tvy;
        out_trans[(size_t)f * 9 + c * 3 + 2] = tvz;
        atomicAdd(&g_sum[vi * 3 + 0], tvx);
        atomicAdd(&g_sum[vi * 3 + 1], tvy);
        atomicAdd(&g_sum[vi * 3 + 2], tvz);
        atomicAdd(&g_cnt[vi], 1.0f);
    }
}

// ===================== finalize segment mean =====================
__global__ void finalize_kernel(float* __restrict__ out_vfeat) {
    int v = blockIdx.x * blockDim.x + threadIdx.x;
    if (v >= N_VERTS) return;
    float c = fmaxf(g_cnt[v], 1.0f);
    float inv = 1.0f / c;
    out_vfeat[v * 3 + 0] = g_sum[v * 3 + 0] * inv;
    out_vfeat[v * 3 + 1] = g_sum[v * 3 + 1] * inv;
    out_vfeat[v * 3 + 2] = g_sum[v * 3 + 2] * inv;
}

// ===================== launch =====================
extern "C" void kernel_launch(void* const* d_in, const int* in_sizes, int n_in,
                              void* d_out, int out_size) {
    const float* verts    = (const float*)d_in[0];
    const float* features = (const float*)d_in[1];
    const int*   faces    = (const int*)d_in[2];
    const float* W1 = (const float*)d_in[3];
    const float* b1 = (const float*)d_in[4];
    const float* W2 = (const float*)d_in[5];
    const float* b2 = (const float*)d_in[6];
    const float* W3 = (const float*)d_in[7];
    const float* b3 = (const float*)d_in[8];
    const float* W4 = (const float*)d_in[9];
    const float* b4 = (const float*)d_in[10];

    float* out = (float*)d_out;
    float* out_vfeat = out;
    float* out_trans = out + (size_t)N_VERTS * 3;
    float* out_rot   = out_trans + (size_t)N_FACES * 9;

    __nv_bfloat16 *p_f_hi, *p_f_lo, *p_x_hi, *p_x_lo, *p_y_hi, *p_y_lo;
    __nv_bfloat16 *p_w1h, *p_w1l, *p_w2h, *p_w2l, *p_w3h, *p_w3l;
    float *p_G, *p_h3, *p_out12;
    cudaGetSymbolAddress((void**)&p_f_hi, g_f_hi);
    cudaGetSymbolAddress((void**)&p_f_lo, g_f_lo);
    cudaGetSymbolAddress((void**)&p_G, g_G);
    cudaGetSymbolAddress((void**)&p_x_hi, g_x_hi);
    cudaGetSymbolAddress((void**)&p_x_lo, g_x_lo);
    cudaGetSymbolAddress((void**)&p_y_hi, g_y_hi);
    cudaGetSymbolAddress((void**)&p_y_lo, g_y_lo);
    cudaGetSymbolAddress((void**)&p_w1h, g_w1t_hi);
    cudaGetSymbolAddress((void**)&p_w1l, g_w1t_lo);
    cudaGetSymbolAddress((void**)&p_w2h, g_w2t_hi);
    cudaGetSymbolAddress((void**)&p_w2l, g_w2t_lo);
    cudaGetSymbolAddress((void**)&p_w3h, g_w3t_hi);
    cudaGetSymbolAddress((void**)&p_w3l, g_w3t_lo);
    cudaGetSymbolAddress((void**)&p_h3, g_h3);
    cudaGetSymbolAddress((void**)&p_out12, g_out12);

    cudaFuncSetAttribute(gemm_hmma<512, 0>,
                         cudaFuncAttributeMaxDynamicSharedMemorySize, SM_TOTAL_G);
    cudaFuncSetAttribute(gemm_hmma<512, 2>,
                         cudaFuncAttributeMaxDynamicSharedMemorySize, SM_TOTAL_G);
    cudaFuncSetAttribute(gemm_hmma<256, 1>,
                         cudaFuncAttributeMaxDynamicSharedMemorySize, SM_TOTAL_G);

    // 1. zero accumulators
    zero_kernel<<<(N_VERTS * 3 + 255) / 256, 256>>>();

    // 2. weight transpose + split
    convert_w_kernel<<<(DIM * DIM + 255) / 256, 256>>>(W1, p_w1h, p_w1l, DIM, DIM);
    convert_w_kernel<<<(DIM * DIM + 255) / 256, 256>>>(W2, p_w2h, p_w2l, DIM, DIM);
    convert_w_kernel<<<(DIM * 256 + 255) / 256, 256>>>(W3, p_w3h, p_w3l, DIM, 256);

    // 3. split features -> bf16 hi/lo (per-vertex)
    split_rows_kernel<<<N_VERTS, 128>>>(features, p_f_hi, p_f_lo);

    // 4. G = features @ W1  (M = N_VERTS, raw f32 out)
    {
        dim3 blk(256);
        dim3 gG(4, (N_VERTS + 127) / 128);
        gemm_hmma<512, 2><<<gG, blk, SM_TOTAL_G>>>(p_f_hi, p_f_lo, p_w1h, p_w1l,
                                                   nullptr, p_G, nullptr, N_VERTS);
    }

    // 5. h1 = relu(mean(G rows) + b1) -> bf16 split (per-face)
    gather_relu_split_kernel<<<N_FACES, 128>>>(p_G, faces, b1, p_x_hi, p_x_lo);

    // 6. layers 2-4
    {
        dim3 blk(256);
        dim3 g12(4, (N_FACES + 127) / 128);
        gemm_hmma<512, 0><<<g12, blk, SM_TOTAL_G>>>(p_x_hi, p_x_lo, p_w2h, p_w2l,
                                                    b2, p_y_hi, p_y_lo, N_FACES);
        dim3 g3(2, (N_FACES + 127) / 128);
        gemm_hmma<256, 1><<<g3, blk, SM_TOTAL_G>>>(p_y_hi, p_y_lo, p_w3h, p_w3l,
                                                   b3, p_h3, nullptr, N_FACES);
        gemm4_kernel<<<(N_FACES + 3) / 4, 128>>>(p_h3, W4, b4, p_out12);
    }

    // 7. procrustes + transform + scatter
    procrustes_kernel<<<(N_FACES + 255) / 256, 256>>>(p_out12, verts, faces,
                                                      out_trans, out_rot);

    // 8. segment mean
    finalize_kernel<<<(N_VERTS + 255) / 256, 256>>>(out_vfeat);
}

// round 8
// speedup vs baseline: 3.1302x; 1.3386x over previous
#include <cuda_runtime.h>
#include <cuda_fp16.h>
#include <math.h>
#include <stdint.h>

#define N_VERTS 100000
#define N_FACES 200000
#define DIM 512

// ===================== portable PTX helpers (sm_80+) =====================
__device__ __forceinline__ uint32_t smem_to_u32(const void* smem_ptr) {
    uint32_t addr;
    asm("{ .reg .u64 tmp; cvta.to.shared.u64 tmp, %1; cvt.u32.u64 %0, tmp; }"
        : "=r"(addr) : "l"(smem_ptr));
    return addr;
}

__device__ __forceinline__ void cp16(uint32_t dst, const void* src) {
    asm volatile("cp.async.cg.shared.global [%0], [%1], 16;"
                 :: "r"(dst), "l"(src) : "memory");
}

__device__ __forceinline__ void ldm_x4(uint32_t (&r)[4], uint32_t addr) {
    asm volatile("ldmatrix.sync.aligned.m8n8.x4.shared.b16 {%0,%1,%2,%3}, [%4];"
                 : "=r"(r[0]), "=r"(r[1]), "=r"(r[2]), "=r"(r[3]) : "r"(addr));
}

__device__ __forceinline__ void mma_f16(float (&d)[4], const uint32_t (&a)[4],
                                        uint32_t b0, uint32_t b1) {
    asm volatile(
        "mma.sync.aligned.m16n8k16.row.col.f32.f16.f16.f32 "
        "{%0,%1,%2,%3}, {%4,%5,%6,%7}, {%8,%9}, {%0,%1,%2,%3};"
        : "+f"(d[0]), "+f"(d[1]), "+f"(d[2]), "+f"(d[3])
        : "r"(a[0]), "r"(a[1]), "r"(a[2]), "r"(a[3]), "r"(b0), "r"(b1));
}

__device__ __forceinline__ uint32_t pack_h2(float a, float b) {
    __half2 t = __floats2half2_rn(a, b);
    return *(uint32_t*)&t;
}

// ===================== scratch (no allocations allowed) =====================
__device__ __half g_f_hi[(size_t)N_VERTS * DIM];   // split features
__device__ __half g_f_lo[(size_t)N_VERTS * DIM];
__device__ float  g_G[(size_t)N_VERTS * DIM];      // features @ W1
__device__ __half g_x_hi[(size_t)N_FACES * DIM];
__device__ __half g_x_lo[(size_t)N_FACES * DIM];
__device__ __half g_y_hi[(size_t)N_FACES * DIM];
__device__ __half g_y_lo[(size_t)N_FACES * DIM];
__device__ float  g_h3[(size_t)N_FACES * 256];
__device__ float  g_out12[(size_t)N_FACES * 12];
__device__ float  g_sum[N_VERTS * 3];
__device__ float  g_cnt[N_VERTS];
// transposed fp16 weights: Wt[n][k] = fp16(W[k][n])
__device__ __half g_w1t[DIM * DIM];
__device__ __half g_w2t[DIM * DIM];
__device__ __half g_w3t[256 * DIM];

// ===================== zero accumulators =====================
__global__ void zero_kernel() {
    int i = blockIdx.x * blockDim.x + threadIdx.x;
    if (i < N_VERTS * 3) g_sum[i] = 0.0f;
    if (i < N_VERTS) g_cnt[i] = 0.0f;
}

// ===================== weight transpose -> fp16 =====================
__global__ void convert_w_kernel(const float* __restrict__ W,
                                 __half* __restrict__ T, int K, int N) {
    int id = blockIdx.x * blockDim.x + threadIdx.x;
    if (id >= K * N) return;
    int k = id / N, n = id % N;
    T[(size_t)n * K + k] = __float2half_rn(W[id]);
}

// ===================== split f32 rows -> fp16 hi/lo =====================
__global__ void split_rows_kernel(const float* __restrict__ in,
                                  __half* __restrict__ outHi,
                                  __half* __restrict__ outLo) {
    int r = blockIdx.x;
    int c = threadIdx.x;  // 128 threads x float4
    float4 x = ((const float4*)(in + (size_t)r * DIM))[c];
    float v[4] = {x.x, x.y, x.z, x.w};
    uint32_t ph[2], pl[2];
#pragma unroll
    for (int p = 0; p < 2; p++) {
        __half h0 = __float2half_rn(v[2 * p]);
        __half h1 = __float2half_rn(v[2 * p + 1]);
        ph[p] = (uint32_t)__half_as_ushort(h0) |
                ((uint32_t)__half_as_ushort(h1) << 16);
        pl[p] = pack_h2(v[2 * p] - __half2float(h0),
                        v[2 * p + 1] - __half2float(h1));
    }
    *(uint2*)(outHi + (size_t)r * DIM + c * 4) = make_uint2(ph[0], ph[1]);
    *(uint2*)(outLo + (size_t)r * DIM + c * 4) = make_uint2(pl[0], pl[1]);
}

// ===================== gather G rows + mean + bias + relu + split ==========
__global__ void gather_relu_split_kernel(const float* __restrict__ G,
                                         const int* __restrict__ faces,
                                         const float* __restrict__ b1,
                                         __half* __restrict__ outHi,
                                         __half* __restrict__ outLo) {
    int f = blockIdx.x;
    int c = threadIdx.x;  // 128 threads x float4
    int i0 = faces[f * 3 + 0];
    int i1 = faces[f * 3 + 1];
    int i2 = faces[f * 3 + 2];
    float4 a = ((const float4*)(G + (size_t)i0 * DIM))[c];
    float4 b = ((const float4*)(G + (size_t)i1 * DIM))[c];
    float4 d = ((const float4*)(G + (size_t)i2 * DIM))[c];
    float4 bb = __ldg((const float4*)&b1[c * 4]);
    const float k3 = 1.0f / 3.0f;
    float v[4];
    v[0] = fmaxf(fmaf(a.x + b.x + d.x, k3, bb.x), 0.0f);
    v[1] = fmaxf(fmaf(a.y + b.y + d.y, k3, bb.y), 0.0f);
    v[2] = fmaxf(fmaf(a.z + b.z + d.z, k3, bb.z), 0.0f);
    v[3] = fmaxf(fmaf(a.w + b.w + d.w, k3, bb.w), 0.0f);
    uint32_t ph[2], pl[2];
#pragma unroll
    for (int p = 0; p < 2; p++) {
        __half h0 = __float2half_rn(v[2 * p]);
        __half h1 = __float2half_rn(v[2 * p + 1]);
        ph[p] = (uint32_t)__half_as_ushort(h0) |
                ((uint32_t)__half_as_ushort(h1) << 16);
        pl[p] = pack_h2(v[2 * p] - __half2float(h0),
                        v[2 * p + 1] - __half2float(h1));
    }
    *(uint2*)(outHi + (size_t)f * DIM + c * 4) = make_uint2(ph[0], ph[1]);
    *(uint2*)(outLo + (size_t)f * DIM + c * 4) = make_uint2(pl[0], pl[1]);
}

// ===================== HMMA 2-pass fp16 GEMM (2-stage, 2 CTAs/SM) ==========
// out = act(A_full @ fp16(Wt)^T + bias); A given exactly as fp16 hi+lo.
// Passes per k16: Ah*W, Al*W  (== (Ah+Al)*W = A*W).
// OUT_MODE 0: relu+bias -> fp16 hi/lo.  1: relu+bias -> f32.  2: raw -> f32.
#define ROW_B       80              // 64B data + 16B pad per smem row
#define BUF_BYTES   (128 * ROW_B)   // 10240
#define STG_BYTES   (3 * BUF_BYTES) // 30720 (Ahi, Alo, B)
#define SM_TOTAL_G  67584           // max(2*STG_BYTES, 128*132*4 epilogue)

template <int N_TOTAL, int OUT_MODE>
__global__ void __launch_bounds__(256, 2)
gemm_hmma(const __half* __restrict__ Ahi,
          const __half* __restrict__ Alo,
          const __half* __restrict__ Bw,
          const float* __restrict__ bias,
          void* __restrict__ outHiV, void* __restrict__ outLoV,
          int M) {
    extern __shared__ char smem[];
    const uint32_t su = smem_to_u32(smem);
    const int tid = threadIdx.x;
    const int m0 = blockIdx.y * 128;
    const int n0 = blockIdx.x * 128;

    const int lane = tid & 31;
    const int warp = tid >> 5;
    const int wm = warp & 3;   // 4 warps along M
    const int wn = warp >> 2;  // 2 warps along N

    const uint32_t aRow = wm * 32 + (lane & 15);
    const uint32_t aCol = (lane >> 4) * 16;
    const uint32_t bRow = wn * 64 + (lane & 7) + ((lane & 16) >> 1);
    const uint32_t bCol = (lane & 8) ? 16u : 0u;

    const uint32_t aHiB = su + aRow * ROW_B + aCol;                  // buf0
    const uint32_t aLoB = aHiB + BUF_BYTES;                          // buf1
    const uint32_t bB   = su + 2 * BUF_BYTES + bRow * ROW_B + bCol;  // buf2

    const int ldRowHalf = tid >> 2;
    const int ldQ = tid & 3;

    float acc[2][8][4];
#pragma unroll
    for (int t = 0; t < 2; t++)
#pragma unroll
        for (int j = 0; j < 8; j++)
#pragma unroll
            for (int e = 0; e < 4; e++) acc[t][j][e] = 0.0f;

    auto load_stage = [&](int stage, int kc) {
        const int k0 = kc * 32;
        const uint32_t stageBase = (uint32_t)stage * STG_BYTES;
#pragma unroll
        for (int i = 0; i < 6; i++) {
            const int buf = i >> 1;
            const int r = (i & 1) * 64 + ldRowHalf;
            const uint32_t dst = su + stageBase + buf * BUF_BYTES +
                                 r * ROW_B + ldQ * 16;
            const __half* srcp;
            if (buf == 0) {
                int gr = m0 + r; if (gr >= M) gr = M - 1;
                srcp = Ahi + (size_t)gr * DIM + k0 + ldQ * 8;
            } else if (buf == 1) {
                int gr = m0 + r; if (gr >= M) gr = M - 1;
                srcp = Alo + (size_t)gr * DIM + k0 + ldQ * 8;
            } else {
                srcp = Bw + (size_t)(n0 + r) * DIM + k0 + ldQ * 8;
            }
            cp16(dst, srcp);
        }
        asm volatile("cp.async.commit_group;" ::: "memory");
    };

    load_stage(0, 0);
    load_stage(1, 1);

    for (int kc = 0; kc < 16; kc++) {
        if (kc == 15) {
            asm volatile("cp.async.wait_group 0;" ::: "memory");
        } else {
            asm volatile("cp.async.wait_group 1;" ::: "memory");
        }
        __syncthreads();

        const uint32_t sb = (uint32_t)(kc & 1) * STG_BYTES;
#pragma unroll
        for (int h = 0; h < 2; h++) {
            const uint32_t hoff = sb + h * 32;
            uint32_t ah[2][4], al[2][4];
            ldm_x4(ah[0], aHiB + hoff);
            ldm_x4(ah[1], aHiB + hoff + 16 * ROW_B);
            ldm_x4(al[0], aLoB + hoff);
            ldm_x4(al[1], aLoB + hoff + 16 * ROW_B);
#pragma unroll
            for (int p = 0; p < 4; p++) {
                uint32_t bw[4];
                ldm_x4(bw, bB + hoff + p * (16 * ROW_B));
#pragma unroll
                for (int t = 0; t < 2; t++) {
                    mma_f16(acc[t][2 * p],     ah[t], bw[0], bw[1]);
                    mma_f16(acc[t][2 * p + 1], ah[t], bw[2], bw[3]);
                    mma_f16(acc[t][2 * p],     al[t], bw[0], bw[1]);
                    mma_f16(acc[t][2 * p + 1], al[t], bw[2], bw[3]);
                }
            }
        }
        __syncthreads();
        if (kc + 2 < 16) load_stage(kc & 1, kc + 2);
    }

    // -------- epilogue --------
    float* sout = (float*)smem;
#pragma unroll
    for (int t = 0; t < 2; t++)
#pragma unroll
        for (int j = 0; j < 8; j++) {
            const int row = wm * 32 + t * 16 + (lane >> 2);
            const int col = wn * 64 + j * 8 + (lane & 3) * 2;
            sout[row * 132 + col]           = acc[t][j][0];
            sout[row * 132 + col + 1]       = acc[t][j][1];
            sout[(row + 8) * 132 + col]     = acc[t][j][2];
            sout[(row + 8) * 132 + col + 1] = acc[t][j][3];
        }
    __syncthreads();

#pragma unroll
    for (int i = 0; i < 16; i++) {
        const int lin = tid + i * 256;
        const int row = lin >> 5;
        const int q = lin & 31;
        const int gr = m0 + row;
        if (gr >= M) continue;
        float4 v = *(float4*)&sout[row * 132 + q * 4];
        if (OUT_MODE != 2) {
            const float4 bb = __ldg((const float4*)&bias[n0 + q * 4]);
            v.x = fmaxf(v.x + bb.x, 0.0f);
            v.y = fmaxf(v.y + bb.y, 0.0f);
            v.z = fmaxf(v.z + bb.z, 0.0f);
            v.w = fmaxf(v.w + bb.w, 0.0f);
        }
        if (OUT_MODE == 0) {
            __half h0 = __float2half_rn(v.x);
            __half h1 = __float2half_rn(v.y);
            __half h2 = __float2half_rn(v.z);
            __half h3 = __float2half_rn(v.w);
            uint2 vh, vl;
            vh.x = (uint32_t)__half_as_ushort(h0) |
                   ((uint32_t)__half_as_ushort(h1) << 16);
            vh.y = (uint32_t)__half_as_ushort(h2) |
                   ((uint32_t)__half_as_ushort(h3) << 16);
            vl.x = pack_h2(v.x - __half2float(h0), v.y - __half2float(h1));
            vl.y = pack_h2(v.z - __half2float(h2), v.w - __half2float(h3));
            const size_t off = (size_t)gr * N_TOTAL + n0 + q * 4;
            *(uint2*)((__half*)outHiV + off) = vh;
            *(uint2*)((__half*)outLoV + off) = vl;
        } else {
            *(float4*)((float*)outHiV + (size_t)gr * N_TOTAL + n0 + q * 4) = v;
        }
    }
}

// ===================== final tiny GEMM =====================
__global__ void gemm4_kernel(const float* __restrict__ A, const float* __restrict__ W4,
                             const float* __restrict__ b4, float* __restrict__ out12) {
    __shared__ float Ws[12][256];
    __shared__ float bs[12];
    int tid = threadIdx.x;  // 128
    for (int i = tid; i < 256 * 12; i += 128) {
        int k = i / 12, j = i % 12;
        Ws[j][k] = W4[i];
    }
    if (tid < 12) bs[tid] = b4[tid];
    __syncthreads();

    int warp = tid >> 5, lane = tid & 31;
    int row = blockIdx.x * 4 + warp;
    if (row >= N_FACES) return;
    const float* a = A + (size_t)row * 256;
    float acc[12];
#pragma unroll
    for (int j = 0; j < 12; j++) acc[j] = 0.0f;
    for (int k = lane; k < 256; k += 32) {
        float h = a[k];
#pragma unroll
        for (int j = 0; j < 12; j++) acc[j] += h * Ws[j][k];
    }
#pragma unroll
    for (int j = 0; j < 12; j++) {
#pragma unroll
        for (int off = 16; off; off >>= 1)
            acc[j] += __shfl_down_sync(0xffffffffu, acc[j], off);
    }
    if (lane == 0) {
#pragma unroll
        for (int j = 0; j < 12; j++) out12[(size_t)row * 12 + j] = acc[j] + bs[j];
    }
}

// ===================== procrustes + transform + scatter =====================
__device__ __forceinline__ void jrot(double A[3][3], double V[3][3], int p, int q) {
    double apq = A[p][q];
    if (fabs(apq) < 1e-300) return;
    double tau = (A[q][q] - A[p][p]) / (2.0 * apq);
    double t = copysign(1.0, tau) / (fabs(tau) + sqrt(1.0 + tau * tau));
    double c = 1.0 / sqrt(1.0 + t * t);
    double s = t * c;
#pragma unroll
    for (int k = 0; k < 3; k++) {
        double akp = A[k][p], akq = A[k][q];
        A[k][p] = c * akp - s * akq;
        A[k][q] = s * akp + c * akq;
    }
#pragma unroll
    for (int k = 0; k < 3; k++) {
        double apk = A[p][k], aqk = A[q][k];
        A[p][k] = c * apk - s * aqk;
        A[q][k] = s * apk + c * aqk;
    }
#pragma unroll
    for (int k = 0; k < 3; k++) {
        double vkp = V[k][p], vkq = V[k][q];
        V[k][p] = c * vkp - s * vkq;
        V[k][q] = s * vkp + c * vkq;
    }
}

__global__ void procrustes_kernel(const float* __restrict__ out12,
                                  const float* __restrict__ verts,
                                  const int* __restrict__ faces,
                                  float* __restrict__ out_trans,
                                  float* __restrict__ out_rot) {
    int f = blockIdx.x * blockDim.x + threadIdx.x;
    if (f >= N_FACES) return;

    double Mm[3][3];
#pragma unroll
    for (int i = 0; i < 3; i++)
#pragma unroll
        for (int j = 0; j < 3; j++)
            Mm[i][j] = (double)out12[(size_t)f * 12 + i * 3 + j];

    double A[3][3], V[3][3];
#pragma unroll
    for (int i = 0; i < 3; i++)
#pragma unroll
        for (int j = 0; j < 3; j++) {
            double s = 0.0;
#pragma unroll
            for (int k = 0; k < 3; k++) s += Mm[k][i] * Mm[k][j];
            A[i][j] = s;
            V[i][j] = (i == j) ? 1.0 : 0.0;
        }

#pragma unroll
    for (int sweep = 0; sweep < 6; sweep++) {
        jrot(A, V, 0, 1);
        jrot(A, V, 0, 2);
        jrot(A, V, 1, 2);
    }

    double lam[3] = {A[0][0], A[1][1], A[2][2]};
#pragma unroll
    for (int a = 0; a < 2; a++) {
        int mx = a;
#pragma unroll
        for (int b = 0; b < 3; b++)
            if (b > a && lam[b] > lam[mx]) mx = b;
        if (mx != a) {
            double tl = lam[a]; lam[a] = lam[mx]; lam[mx] = tl;
#pragma unroll
            for (int k = 0; k < 3; k++) {
                double tv = V[k][a]; V[k][a] = V[k][mx]; V[k][mx] = tv;
            }
        }
    }

    double Bc[3][3];
#pragma unroll
    for (int i = 0; i < 3; i++)
#pragma unroll
        for (int k = 0; k < 3; k++) {
            double s = 0.0;
#pragma unroll
            for (int j = 0; j < 3; j++) s += Mm[i][j] * V[j][k];
            Bc[i][k] = s;
        }

    double u1[3], u2[3], u3[3];
    double n1 = sqrt(Bc[0][0] * Bc[0][0] + Bc[1][0] * Bc[1][0] + Bc[2][0] * Bc[2][0]);
    double in1 = 1.0 / fmax(n1, 1e-150);
#pragma unroll
    for (int i = 0; i < 3; i++) u1[i] = Bc[i][0] * in1;
    double d12 = u1[0] * Bc[0][1] + u1[1] * Bc[1][1] + u1[2] * Bc[2][1];
    double w[3];
#pragma unroll
    for (int i = 0; i < 3; i++) w[i] = Bc[i][1] - d12 * u1[i];
    double n2 = sqrt(w[0] * w[0] + w[1] * w[1] + w[2] * w[2]);
    double in2 = 1.0 / fmax(n2, 1e-150);
#pragma unroll
    for (int i = 0; i < 3; i++) u2[i] = w[i] * in2;
    u3[0] = u1[1] * u2[2] - u1[2] * u2[1];
    u3[1] = u1[2] * u2[0] - u1[0] * u2[2];
    u3[2] = u1[0] * u2[1] - u1[1] * u2[0];

    double detV = V[0][0] * (V[1][1] * V[2][2] - V[1][2] * V[2][1])
                - V[0][1] * (V[1][0] * V[2][2] - V[1][2] * V[2][0])
                + V[0][2] * (V[1][0] * V[2][1] - V[1][1] * V[2][0]);

    float R[3][3];
#pragma unroll
    for (int i = 0; i < 3; i++)
#pragma unroll
        for (int j = 0; j < 3; j++)
            R[i][j] = (float)(u1[i] * V[j][0] + u2[i] * V[j][1] + detV * u3[i] * V[j][2]);

#pragma unroll
    for (int i = 0; i < 3; i++)
#pragma unroll
        for (int j = 0; j < 3; j++)
            out_rot[(size_t)f * 9 + i * 3 + j] = R[i][j];

    float t0 = out12[(size_t)f * 12 + 9];
    float t1 = out12[(size_t)f * 12 + 10];
    float t2 = out12[(size_t)f * 12 + 11];

#pragma unroll
    for (int c = 0; c < 3; c++) {
        int vi = faces[f * 3 + c];
        float vx = verts[(size_t)vi * 3 + 0];
        float vy = verts[(size_t)vi * 3 + 1];
        float vz = verts[(size_t)vi * 3 + 2];
        float tvx = vx * R[0][0] + vy * R[1][0] + vz * R[2][0] + t0;
        float tvy = vx * R[0][1] + vy * R[1][1] + vz * R[2][1] + t1;
        float tvz = vx * R[0][2] + vy * R[1][2] + vz * R[2][2] + t2;
        out_trans[(size_t)f * 9 + c * 3 + 0] = tvx;
        out_trans[(size_t)f * 9 + c * 3 + 1] = tvy;
        out_trans[(size_t)f * 9 + c * 3 + 2] = tvz;
        atomicAdd(&g_sum[vi * 3 + 0], tvx);
        atomicAdd(&g_sum[vi * 3 + 1], tvy);
        atomicAdd(&g_sum[vi * 3 + 2], tvz);
        atomicAdd(&g_cnt[vi], 1.0f);
    }
}

// ===================== finalize segment mean =====================
__global__ void finalize_kernel(float* __restrict__ out_vfeat) {
    int v = blockIdx.x * blockDim.x + threadIdx.x;
    if (v >= N_VERTS) return;
    float c = fmaxf(g_cnt[v], 1.0f);
    float inv = 1.0f / c;
    out_vfeat[v * 3 + 0] = g_sum[v * 3 + 0] * inv;
    out_vfeat[v * 3 + 1] = g_sum[v * 3 + 1] * inv;
    out_vfeat[v * 3 + 2] = g_sum[v * 3 + 2] * inv;
}

// ===================== launch =====================
extern "C" void kernel_launch(void* const* d_in, const int* in_sizes, int n_in,
                              void* d_out, int out_size) {
    const float* verts    = (const float*)d_in[0];
    const float* features = (const float*)d_in[1];
    const int*   faces    = (const int*)d_in[2];
    const float* W1 = (const float*)d_in[3];
    const float* b1 = (const float*)d_in[4];
    const float* W2 = (const float*)d_in[5];
    const float* b2 = (const float*)d_in[6];
    const float* W3 = (const float*)d_in[7];
    const float* b3 = (const float*)d_in[8];
    const float* W4 = (const float*)d_in[9];
    const float* b4 = (const float*)d_in[10];

    float* out = (float*)d_out;
    float* out_vfeat = out;
    float* out_trans = out + (size_t)N_VERTS * 3;
    float* out_rot   = out_trans + (size_t)N_FACES * 9;

    __half *p_f_hi, *p_f_lo, *p_x_hi, *p_x_lo, *p_y_hi, *p_y_lo;
    __half *p_w1t, *p_w2t, *p_w3t;
    float *p_G, *p_h3, *p_out12;
    cudaGetSymbolAddress((void**)&p_f_hi, g_f_hi);
    cudaGetSymbolAddress((void**)&p_f_lo, g_f_lo);
    cudaGetSymbolAddress((void**)&p_G, g_G);
    cudaGetSymbolAddress((void**)&p_x_hi, g_x_hi);
    cudaGetSymbolAddress((void**)&p_x_lo, g_x_lo);
    cudaGetSymbolAddress((void**)&p_y_hi, g_y_hi);
    cudaGetSymbolAddress((void**)&p_y_lo, g_y_lo);
    cudaGetSymbolAddress((void**)&p_w1t, g_w1t);
    cudaGetSymbolAddress((void**)&p_w2t, g_w2t);
    cudaGetSymbolAddress((void**)&p_w3t, g_w3t);
    cudaGetSymbolAddress((void**)&p_h3, g_h3);
    cudaGetSymbolAddress((void**)&p_out12, g_out12);

    cudaFuncSetAttribute(gemm_hmma<512, 0>,
                         cudaFuncAttributeMaxDynamicSharedMemorySize, SM_TOTAL_G);
    cudaFuncSetAttribute(gemm_hmma<512, 2>,
                         cudaFuncAttributeMaxDynamicSharedMemorySize, SM_TOTAL_G);
    cudaFuncSetAttribute(gemm_hmma<256, 1>,
                         cudaFuncAttributeMaxDynamicSharedMemorySize, SM_TOTAL_G);

    // 1. zero accumulators
    zero_kernel<<<(N_VERTS * 3 + 255) / 256, 256>>>();

    // 2. weight transpose -> fp16
    convert_w_kernel<<<(DIM * DIM + 255) / 256, 256>>>(W1, p_w1t, DIM, DIM);
    convert_w_kernel<<<(DIM * DIM + 255) / 256, 256>>>(W2, p_w2t, DIM, DIM);
    convert_w_kernel<<<(DIM * 256 + 255) / 256, 256>>>(W3, p_w3t, DIM, 256);

    // 3. split features -> fp16 hi/lo (per-vertex)
    split_rows_kernel<<<N_VERTS, 128>>>(features, p_f_hi, p_f_lo);

    // 4. G = features @ W1  (M = N_VERTS, raw f32 out)
    {
        dim3 blk(256);
        dim3 gG(4, (N_VERTS + 127) / 128);
        gemm_hmma<512, 2><<<gG, blk, SM_TOTAL_G>>>(p_f_hi, p_f_lo, p_w1t,
                                                   nullptr, p_G, nullptr, N_VERTS);
    }

    // 5. h1 = relu(mean(G rows) + b1) -> fp16 split (per-face)
    gather_relu_split_kernel<<<N_FACES, 128>>>(p_G, faces, b1, p_x_hi, p_x_lo);

    // 6. layers 2-4
    {
        dim3 blk(256);
        dim3 g12(4, (N_FACES + 127) / 128);
        gemm_hmma<512, 0><<<g12, blk, SM_TOTAL_G>>>(p_x_hi, p_x_lo, p_w2t,
                                                    b2, p_y_hi, p_y_lo, N_FACES);
        dim3 g3(2, (N_FACES + 127) / 128);
        gemm_hmma<256, 1><<<g3, blk, SM_TOTAL_G>>>(p_y_hi, p_y_lo, p_w3t,
                                                   b3, p_h3, nullptr, N_FACES);
        gemm4_kernel<<<(N_FACES + 3) / 4, 128>>>(p_h3, W4, b4, p_out12);
    }

    // 7. procrustes + transform + scatter
    procrustes_kernel<<<(N_FACES + 255) / 256, 256>>>(p_out12, verts, faces,
                                                      out_trans, out_rot);

    // 8. segment mean
    finalize_kernel<<<(N_VERTS + 255) / 256, 256>>>(out_vfeat);
}

// round 9
// speedup vs baseline: 3.5705x; 1.1407x over previous
#include <cuda_runtime.h>
#include <cuda_fp16.h>
#include <math.h>
#include <stdint.h>

#define N_VERTS 100000
#define N_FACES 200000
#define DIM 512

// ===================== portable PTX helpers (sm_80+) =====================
__device__ __forceinline__ uint32_t smem_to_u32(const void* smem_ptr) {
    uint32_t addr;
    asm("{ .reg .u64 tmp; cvta.to.shared.u64 tmp, %1; cvt.u32.u64 %0, tmp; }"
        : "=r"(addr) : "l"(smem_ptr));
    return addr;
}

__device__ __forceinline__ void cp16(uint32_t dst, const void* src) {
    asm volatile("cp.async.cg.shared.global [%0], [%1], 16;"
                 :: "r"(dst), "l"(src) : "memory");
}

__device__ __forceinline__ void ldm_x4(uint32_t (&r)[4], uint32_t addr) {
    asm volatile("ldmatrix.sync.aligned.m8n8.x4.shared.b16 {%0,%1,%2,%3}, [%4];"
                 : "=r"(r[0]), "=r"(r[1]), "=r"(r[2]), "=r"(r[3]) : "r"(addr));
}

__device__ __forceinline__ void mma_f16(float (&d)[4], const uint32_t (&a)[4],
                                        uint32_t b0, uint32_t b1) {
    asm volatile(
        "mma.sync.aligned.m16n8k16.row.col.f32.f16.f16.f32 "
        "{%0,%1,%2,%3}, {%4,%5,%6,%7}, {%8,%9}, {%0,%1,%2,%3};"
        : "+f"(d[0]), "+f"(d[1]), "+f"(d[2]), "+f"(d[3])
        : "r"(a[0]), "r"(a[1]), "r"(a[2]), "r"(a[3]), "r"(b0), "r"(b1));
}

__device__ __forceinline__ uint32_t pack_h2(float a, float b) {
    __half2 t = __floats2half2_rn(a, b);
    return *(uint32_t*)&t;
}

// ===================== scratch (no allocations allowed) =====================
__device__ __half g_f_hi[(size_t)N_VERTS * DIM];   // split features
__device__ __half g_f_lo[(size_t)N_VERTS * DIM];
__device__ float  g_G[(size_t)N_VERTS * DIM];      // features @ W1
__device__ __half g_x_hi[(size_t)N_FACES * DIM];
__device__ __half g_x_lo[(size_t)N_FACES * DIM];
__device__ __half g_y_hi[(size_t)N_FACES * DIM];
__device__ __half g_y_lo[(size_t)N_FACES * DIM];
__device__ float  g_p12[2 * (size_t)N_FACES * 12]; // partial out12 per N-block
__device__ float  g_sum[N_VERTS * 3];
__device__ float  g_cnt[N_VERTS];
// transposed fp16 weights: Wt[n][k] = fp16(W[k][n])
__device__ __half g_w1t[DIM * DIM];
__device__ __half g_w2t[DIM * DIM];
__device__ __half g_w3t[256 * DIM];

// ===================== prep: zero accumulators + convert all weights ========
#define PREP_W1   262144              // 512*512
#define PREP_W2   524288
#define PREP_W3   655360              // + 512*256
#define PREP_SUM  955360              // + 300000
#define PREP_CNT  1055360             // + 100000

__global__ void prep_kernel(const float* __restrict__ W1,
                            const float* __restrict__ W2,
                            const float* __restrict__ W3) {
    int id = blockIdx.x * blockDim.x + threadIdx.x;
    if (id < PREP_W1) {
        int k = id / 512, n = id % 512;
        g_w1t[(size_t)n * DIM + k] = __float2half_rn(W1[id]);
    } else if (id < PREP_W2) {
        int i = id - PREP_W1;
        int k = i / 512, n = i % 512;
        g_w2t[(size_t)n * DIM + k] = __float2half_rn(W2[i]);
    } else if (id < PREP_W3) {
        int i = id - PREP_W2;
        int k = i / 256, n = i % 256;
        g_w3t[(size_t)n * DIM + k] = __float2half_rn(W3[i]);
    } else if (id < PREP_SUM) {
        g_sum[id - PREP_W3] = 0.0f;
    } else if (id < PREP_CNT) {
        g_cnt[id - PREP_SUM] = 0.0f;
    }
}

// ===================== split f32 rows -> fp16 hi/lo =====================
__global__ void split_rows_kernel(const float* __restrict__ in,
                                  __half* __restrict__ outHi,
                                  __half* __restrict__ outLo) {
    int r = blockIdx.x;
    int c = threadIdx.x;  // 128 threads x float4
    float4 x = ((const float4*)(in + (size_t)r * DIM))[c];
    float v[4] = {x.x, x.y, x.z, x.w};
    uint32_t ph[2], pl[2];
#pragma unroll
    for (int p = 0; p < 2; p++) {
        __half h0 = __float2half_rn(v[2 * p]);
        __half h1 = __float2half_rn(v[2 * p + 1]);
        ph[p] = (uint32_t)__half_as_ushort(h0) |
                ((uint32_t)__half_as_ushort(h1) << 16);
        pl[p] = pack_h2(v[2 * p] - __half2float(h0),
                        v[2 * p + 1] - __half2float(h1));
    }
    *(uint2*)(outHi + (size_t)r * DIM + c * 4) = make_uint2(ph[0], ph[1]);
    *(uint2*)(outLo + (size_t)r * DIM + c * 4) = make_uint2(pl[0], pl[1]);
}

// ===================== gather G rows + mean + bias + relu + split ==========
__global__ void gather_relu_split_kernel(const float* __restrict__ G,
                                         const int* __restrict__ faces,
                                         const float* __restrict__ b1,
                                         __half* __restrict__ outHi,
                                         __half* __restrict__ outLo) {
    int f = blockIdx.x;
    int c = threadIdx.x;  // 128 threads x float4
    int i0 = faces[f * 3 + 0];
    int i1 = faces[f * 3 + 1];
    int i2 = faces[f * 3 + 2];
    float4 a = ((const float4*)(G + (size_t)i0 * DIM))[c];
    float4 b = ((const float4*)(G + (size_t)i1 * DIM))[c];
    float4 d = ((const float4*)(G + (size_t)i2 * DIM))[c];
    float4 bb = __ldg((const float4*)&b1[c * 4]);
    const float k3 = 1.0f / 3.0f;
    float v[4];
    v[0] = fmaxf(fmaf(a.x + b.x + d.x, k3, bb.x), 0.0f);
    v[1] = fmaxf(fmaf(a.y + b.y + d.y, k3, bb.y), 0.0f);
    v[2] = fmaxf(fmaf(a.z + b.z + d.z, k3, bb.z), 0.0f);
    v[3] = fmaxf(fmaf(a.w + b.w + d.w, k3, bb.w), 0.0f);
    uint32_t ph[2], pl[2];
#pragma unroll
    for (int p = 0; p < 2; p++) {
        __half h0 = __float2half_rn(v[2 * p]);
        __half h1 = __float2half_rn(v[2 * p + 1]);
        ph[p] = (uint32_t)__half_as_ushort(h0) |
                ((uint32_t)__half_as_ushort(h1) << 16);
        pl[p] = pack_h2(v[2 * p] - __half2float(h0),
                        v[2 * p + 1] - __half2float(h1));
    }
    *(uint2*)(outHi + (size_t)f * DIM + c * 4) = make_uint2(ph[0], ph[1]);
    *(uint2*)(outLo + (size_t)f * DIM + c * 4) = make_uint2(pl[0], pl[1]);
}

// ===================== HMMA 2-pass fp16 GEMM (2-stage, 2 CTAs/SM) ==========
// out = act(A_full @ fp16(Wt)^T + bias); A given exactly as fp16 hi+lo.
// OUT_MODE 0: relu+bias -> fp16 hi/lo.
// OUT_MODE 2: raw -> f32.
// OUT_MODE 3: relu+bias, then fused head: p12 = relu_tile @ W4_slice (per N-block).
#define ROW_B       80              // 64B data + 16B pad per smem row
#define BUF_BYTES   (128 * ROW_B)   // 10240
#define STG_BYTES   (3 * BUF_BYTES) // 30720 (Ahi, Alo, B)
#define SOUT_BYTES  67584           // 128*132*4
#define SM_BIAS_OFF SOUT_BYTES
#define SM_W4_OFF   (SOUT_BYTES + 512)
#define SM_TOTAL_G  SOUT_BYTES               // modes 0/2
#define SM_TOTAL_G3 (SOUT_BYTES + 512 + 6144) // mode 3: + sbias + W4 slice

template <int N_TOTAL, int OUT_MODE>
__global__ void __launch_bounds__(256, 2)
gemm_hmma(const __half* __restrict__ Ahi,
          const __half* __restrict__ Alo,
          const __half* __restrict__ Bw,
          const float* __restrict__ bias,
          void* __restrict__ outHiV, void* __restrict__ outLoV,
          int M,
          const float* __restrict__ W4p, float* __restrict__ p12) {
    extern __shared__ char smem[];
    const uint32_t su = smem_to_u32(smem);
    const int tid = threadIdx.x;
    const int m0 = blockIdx.y * 128;
    const int n0 = blockIdx.x * 128;

    // mode-3 preloads live ABOVE the stage buffers -> safe before mainloop
    if (OUT_MODE == 3) {
        float* sbias = (float*)(smem + SM_BIAS_OFF);
        float* w4s = (float*)(smem + SM_W4_OFF);
        if (tid < 128) sbias[tid] = bias[n0 + tid];
        for (int i = tid; i < 128 * 12; i += 256)
            w4s[i] = W4p[(size_t)(n0 + i / 12) * 12 + (i % 12)];
    }

    const int lane = tid & 31;
    const int warp = tid >> 5;
    const int wm = warp & 3;   // 4 warps along M
    const int wn = warp >> 2;  // 2 warps along N

    const uint32_t aRow = wm * 32 + (lane & 15);
    const uint32_t aCol = (lane >> 4) * 16;
    const uint32_t bRow = wn * 64 + (lane & 7) + ((lane & 16) >> 1);
    const uint32_t bCol = (lane & 8) ? 16u : 0u;

    const uint32_t aHiB = su + aRow * ROW_B + aCol;                  // buf0
    const uint32_t aLoB = aHiB + BUF_BYTES;                          // buf1
    const uint32_t bB   = su + 2 * BUF_BYTES + bRow * ROW_B + bCol;  // buf2

    const int ldRowHalf = tid >> 2;
    const int ldQ = tid & 3;

    float acc[2][8][4];
#pragma unroll
    for (int t = 0; t < 2; t++)
#pragma unroll
        for (int j = 0; j < 8; j++)
#pragma unroll
            for (int e = 0; e < 4; e++) acc[t][j][e] = 0.0f;

    auto load_stage = [&](int stage, int kc) {
        const int k0 = kc * 32;
        const uint32_t stageBase = (uint32_t)stage * STG_BYTES;
#pragma unroll
        for (int i = 0; i < 6; i++) {
            const int buf = i >> 1;
            const int r = (i & 1) * 64 + ldRowHalf;
            const uint32_t dst = su + stageBase + buf * BUF_BYTES +
                                 r * ROW_B + ldQ * 16;
            const __half* srcp;
            if (buf == 0) {
                int gr = m0 + r; if (gr >= M) gr = M - 1;
                srcp = Ahi + (size_t)gr * DIM + k0 + ldQ * 8;
            } else if (buf == 1) {
                int gr = m0 + r; if (gr >= M) gr = M - 1;
                srcp = Alo + (size_t)gr * DIM + k0 + ldQ * 8;
            } else {
                srcp = Bw + (size_t)(n0 + r) * DIM + k0 + ldQ * 8;
            }
            cp16(dst, srcp);
        }
        asm volatile("cp.async.commit_group;" ::: "memory");
    };

    load_stage(0, 0);
    load_stage(1, 1);

    for (int kc = 0; kc < 16; kc++) {
        if (kc == 15) {
            asm volatile("cp.async.wait_group 0;" ::: "memory");
        } else {
            asm volatile("cp.async.wait_group 1;" ::: "memory");
        }
        __syncthreads();

        const uint32_t sb = (uint32_t)(kc & 1) * STG_BYTES;
#pragma unroll
        for (int h = 0; h < 2; h++) {
            const uint32_t hoff = sb + h * 32;
            uint32_t ah[2][4], al[2][4];
            ldm_x4(ah[0], aHiB + hoff);
            ldm_x4(ah[1], aHiB + hoff + 16 * ROW_B);
            ldm_x4(al[0], aLoB + hoff);
            ldm_x4(al[1], aLoB + hoff + 16 * ROW_B);
#pragma unroll
            for (int p = 0; p < 4; p++) {
                uint32_t bw[4];
                ldm_x4(bw, bB + hoff + p * (16 * ROW_B));
#pragma unroll
                for (int t = 0; t < 2; t++) {
                    mma_f16(acc[t][2 * p],     ah[t], bw[0], bw[1]);
                    mma_f16(acc[t][2 * p + 1], ah[t], bw[2], bw[3]);
                    mma_f16(acc[t][2 * p],     al[t], bw[0], bw[1]);
                    mma_f16(acc[t][2 * p + 1], al[t], bw[2], bw[3]);
                }
            }
        }
        __syncthreads();
        if (kc + 2 < 16) load_stage(kc & 1, kc + 2);
    }

    // -------- epilogue --------
    float* sout = (float*)smem;
    if (OUT_MODE == 3) {
        // stage with bias + relu applied
        const float* sbias = (const float*)(smem + SM_BIAS_OFF);
#pragma unroll
        for (int t = 0; t < 2; t++)
#pragma unroll
            for (int j = 0; j < 8; j++) {
                const int row = wm * 32 + t * 16 + (lane >> 2);
                const int col = wn * 64 + j * 8 + (lane & 3) * 2;
                sout[row * 132 + col] =
                    fmaxf(acc[t][j][0] + sbias[col], 0.0f);
                sout[row * 132 + col + 1] =
                    fmaxf(acc[t][j][1] + sbias[col + 1], 0.0f);
                sout[(row + 8) * 132 + col] =
                    fmaxf(acc[t][j][2] + sbias[col], 0.0f);
                sout[(row + 8) * 132 + col + 1] =
                    fmaxf(acc[t][j][3] + sbias[col + 1], 0.0f);
            }
        __syncthreads();
        // fused head: p12[row][jh*6..jh*6+5] = sum_c sout[row][c]*W4[c][j]
        const float* w4s = (const float*)(smem + SM_W4_OFF);
        const int row = tid >> 1;
        const int jh = (tid & 1) * 6;
        float p[6] = {0, 0, 0, 0, 0, 0};
        for (int c = 0; c < 128; c++) {
            const float h = sout[row * 132 + c];
#pragma unroll
            for (int jj = 0; jj < 6; jj++)
                p[jj] = fmaf(h, w4s[c * 12 + jh + jj], p[jj]);
        }
        const int gr = m0 + row;
        if (gr < M) {
            float* dst = p12 + ((size_t)blockIdx.x * M + gr) * 12 + jh;
#pragma unroll
            for (int jj = 0; jj < 6; jj++) dst[jj] = p[jj];
        }
        return;
    }

#pragma unroll
    for (int t = 0; t < 2; t++)
#pragma unroll
        for (int j = 0; j < 8; j++) {
            const int row = wm * 32 + t * 16 + (lane >> 2);
            const int col = wn * 64 + j * 8 + (lane & 3) * 2;
            sout[row * 132 + col]           = acc[t][j][0];
            sout[row * 132 + col + 1]       = acc[t][j][1];
            sout[(row + 8) * 132 + col]     = acc[t][j][2];
            sout[(row + 8) * 132 + col + 1] = acc[t][j][3];
        }
    __syncthreads();

#pragma unroll
    for (int i = 0; i < 16; i++) {
        const int lin = tid + i * 256;
        const int row = lin >> 5;
        const int q = lin & 31;
        const int gr = m0 + row;
        if (gr >= M) continue;
        float4 v = *(float4*)&sout[row * 132 + q * 4];
        if (OUT_MODE == 0) {
            const float4 bb = __ldg((const float4*)&bias[n0 + q * 4]);
            v.x = fmaxf(v.x + bb.x, 0.0f);
            v.y = fmaxf(v.y + bb.y, 0.0f);
            v.z = fmaxf(v.z + bb.z, 0.0f);
            v.w = fmaxf(v.w + bb.w, 0.0f);
            __half h0 = __float2half_rn(v.x);
            __half h1 = __float2half_rn(v.y);
            __half h2 = __float2half_rn(v.z);
            __half h3 = __float2half_rn(v.w);
            uint2 vh, vl;
            vh.x = (uint32_t)__half_as_ushort(h0) |
                   ((uint32_t)__half_as_ushort(h1) << 16);
            vh.y = (uint32_t)__half_as_ushort(h2) |
                   ((uint32_t)__half_as_ushort(h3) << 16);
            vl.x = pack_h2(v.x - __half2float(h0), v.y - __half2float(h1));
            vl.y = pack_h2(v.z - __half2float(h2), v.w - __half2float(h3));
            const size_t off = (size_t)gr * N_TOTAL + n0 + q * 4;
            *(uint2*)((__half*)outHiV + off) = vh;
            *(uint2*)((__half*)outLoV + off) = vl;
        } else {
            *(float4*)((float*)outHiV + (size_t)gr * N_TOTAL + n0 + q * 4) = v;
        }
    }
}

// ===================== procrustes + transform + scatter =====================
__device__ __forceinline__ void jrot(double A[3][3], double V[3][3], int p, int q) {
    double apq = A[p][q];
    if (fabs(apq) < 1e-300) return;
    double tau = (A[q][q] - A[p][p]) / (2.0 * apq);
    double t = copysign(1.0, tau) / (fabs(tau) + sqrt(1.0 + tau * tau));
    double c = 1.0 / sqrt(1.0 + t * t);
    double s = t * c;
#pragma unroll
    for (int k = 0; k < 3; k++) {
        double akp = A[k][p], akq = A[k][q];
        A[k][p] = c * akp - s * akq;
        A[k][q] = s * akp + c * akq;
    }
#pragma unroll
    for (int k = 0; k < 3; k++) {
        double apk = A[p][k], aqk = A[q][k];
        A[p][k] = c * apk - s * aqk;
        A[q][k] = s * apk + c * aqk;
    }
#pragma unroll
    for (int k = 0; k < 3; k++) {
        double vkp = V[k][p], vkq = V[k][q];
        V[k][p] = c * vkp - s * vkq;
        V[k][q] = s * vkp + c * vkq;
    }
}

__global__ void procrustes_kernel(const float* __restrict__ p12,
                                  const float* __restrict__ b4,
                                  const float* __restrict__ verts,
                                  const int* __restrict__ faces,
                                  float* __restrict__ out_trans,
                                  float* __restrict__ out_rot) {
    int f = blockIdx.x * blockDim.x + threadIdx.x;
    if (f >= N_FACES) return;

    const size_t HALF = (size_t)N_FACES * 12;
    float o12[12];
#pragma unroll
    for (int j = 0; j < 12; j++)
        o12[j] = p12[(size_t)f * 12 + j] + p12[HALF + (size_t)f * 12 + j] +
                 __ldg(&b4[j]);

    double Mm[3][3];
#pragma unroll
    for (int i = 0; i < 3; i++)
#pragma unroll
        for (int j = 0; j < 3; j++)
            Mm[i][j] = (double)o12[i * 3 + j];

    double A[3][3], V[3][3];
#pragma unroll
    for (int i = 0; i < 3; i++)
#pragma unroll
        for (int j = 0; j < 3; j++) {
            double s = 0.0;
#pragma unroll
            for (int k = 0; k < 3; k++) s += Mm[k][i] * Mm[k][j];
            A[i][j] = s;
            V[i][j] = (i == j) ? 1.0 : 0.0;
        }

#pragma unroll
    for (int sweep = 0; sweep < 6; sweep++) {
        jrot(A, V, 0, 1);
        jrot(A, V, 0, 2);
        jrot(A, V, 1, 2);
    }

    double lam[3] = {A[0][0], A[1][1], A[2][2]};
#pragma unroll
    for (int a = 0; a < 2; a++) {
        int mx = a;
#pragma unroll
        for (int b = 0; b < 3; b++)
            if (b > a && lam[b] > lam[mx]) mx = b;
        if (mx != a) {
            double tl = lam[a]; lam[a] = lam[mx]; lam[mx] = tl;
#pragma unroll
            for (int k = 0; k < 3; k++) {
                double tv = V[k][a]; V[k][a] = V[k][mx]; V[k][mx] = tv;
            }
        }
    }

    double Bc[3][3];
#pragma unroll
    for (int i = 0; i < 3; i++)
#pragma unroll
        for (int k = 0; k < 3; k++) {
            double s = 0.0;
#pragma unroll
            for (int j = 0; j < 3; j++) s += Mm[i][j] * V[j][k];
            Bc[i][k] = s;
        }

    double u1[3], u2[3], u3[3];
    double n1 = sqrt(Bc[0][0] * Bc[0][0] + Bc[1][0] * Bc[1][0] + Bc[2][0] * Bc[2][0]);
    double in1 = 1.0 / fmax(n1, 1e-150);
#pragma unroll
    for (int i = 0; i < 3; i++) u1[i] = Bc[i][0] * in1;
    double d12 = u1[0] * Bc[0][1] + u1[1] * Bc[1][1] + u1[2] * Bc[2][1];
    double w[3];
#pragma unroll
    for (int i = 0; i < 3; i++) w[i] = Bc[i][1] - d12 * u1[i];
    double n2 = sqrt(w[0] * w[0] + w[1] * w[1] + w[2] * w[2]);
    double in2 = 1.0 / fmax(n2, 1e-150);
#pragma unroll
    for (int i = 0; i < 3; i++) u2[i] = w[i] * in2;
    u3[0] = u1[1] * u2[2] - u1[2] * u2[1];
    u3[1] = u1[2] * u2[0] - u1[0] * u2[2];
    u3[2] = u1[0] * u2[1] - u1[1] * u2[0];

    double detV = V[0][0] * (V[1][1] * V[2][2] - V[1][2] * V[2][1])
                - V[0][1] * (V[1][0] * V[2][2] - V[1][2] * V[2][0])
                + V[0][2] * (V[1][0] * V[2][1] - V[1][1] * V[2][0]);

    float R[3][3];
#pragma unroll
    for (int i = 0; i < 3; i++)
#pragma unroll
        for (int j = 0; j < 3; j++)
            R[i][j] = (float)(u1[i] * V[j][0] + u2[i] * V[j][1] + detV * u3[i] * V[j][2]);

#pragma unroll
    for (int i = 0; i < 3; i++)
#pragma unroll
        for (int j = 0; j < 3; j++)
            out_rot[(size_t)f * 9 + i * 3 + j] = R[i][j];

    float t0 = o12[9];
    float t1 = o12[10];
    float t2 = o12[11];

#pragma unroll
    for (int c = 0; c < 3; c++) {
        int vi = faces[f * 3 + c];
        float vx = verts[(size_t)vi * 3 + 0];
        float vy = verts[(size_t)vi * 3 + 1];
        float vz = verts[(size_t)vi * 3 + 2];
        float tvx = vx * R[0][0] + vy * R[1][0] + vz * R[2][0] + t0;
        float tvy = vx * R[0][1] + vy * R[1][1] + vz * R[2][1] + t1;
        float tvz = vx * R[0][2] + vy * R[1][2] + vz * R[2][2] + t2;
        out_trans[(size_t)f * 9 + c * 3 + 0] = tvx;
        out_trans[(size_t)f * 9 + c * 3 + 1] = tvy;
        out_trans[(size_t)f * 9 + c * 3 + 2] = tvz;
        atomicAdd(&g_sum[vi * 3 + 0], tvx);
        atomicAdd(&g_sum[vi * 3 + 1], tvy);
        atomicAdd(&g_sum[vi * 3 + 2], tvz);
        atomicAdd(&g_cnt[vi], 1.0f);
    }
}

// ===================== finalize segment mean =====================
__global__ void finalize_kernel(float* __restrict__ out_vfeat) {
    int v = blockIdx.x * blockDim.x + threadIdx.x;
    if (v >= N_VERTS) return;
    float c = fmaxf(g_cnt[v], 1.0f);
    float inv = 1.0f / c;
    out_vfeat[v * 3 + 0] = g_sum[v * 3 + 0] * inv;
    out_vfeat[v * 3 + 1] = g_sum[v * 3 + 1] * inv;
    out_vfeat[v * 3 + 2] = g_sum[v * 3 + 2] * inv;
}

// ===================== launch =====================
extern "C" void kernel_launch(void* const* d_in, const int* in_sizes, int n_in,
                              void* d_out, int out_size) {
    const float* verts    = (const float*)d_in[0];
    const float* features = (const float*)d_in[1];
    const int*   faces    = (const int*)d_in[2];
    const float* W1 = (const float*)d_in[3];
    const float* b1 = (const float*)d_in[4];
    const float* W2 = (const float*)d_in[5];
    const float* b2 = (const float*)d_in[6];
    const float* W3 = (const float*)d_in[7];
    const float* b3 = (const float*)d_in[8];
    const float* W4 = (const float*)d_in[9];
    const float* b4 = (const float*)d_in[10];

    float* out = (float*)d_out;
    float* out_vfeat = out;
    float* out_trans = out + (size_t)N_VERTS * 3;
    float* out_rot   = out_trans + (size_t)N_FACES * 9;

    __half *p_f_hi, *p_f_lo, *p_x_hi, *p_x_lo, *p_y_hi, *p_y_lo;
    __half *p_w1t, *p_w2t, *p_w3t;
    float *p_G, *p_p12;
    cudaGetSymbolAddress((void**)&p_f_hi, g_f_hi);
    cudaGetSymbolAddress((void**)&p_f_lo, g_f_lo);
    cudaGetSymbolAddress((void**)&p_G, g_G);
    cudaGetSymbolAddress((void**)&p_x_hi, g_x_hi);
    cudaGetSymbolAddress((void**)&p_x_lo, g_x_lo);
    cudaGetSymbolAddress((void**)&p_y_hi, g_y_hi);
    cudaGetSymbolAddress((void**)&p_y_lo, g_y_lo);
    cudaGetSymbolAddress((void**)&p_w1t, g_w1t);
    cudaGetSymbolAddress((void**)&p_w2t, g_w2t);
    cudaGetSymbolAddress((void**)&p_w3t, g_w3t);
    cudaGetSymbolAddress((void**)&p_p12, g_p12);

    cudaFuncSetAttribute(gemm_hmma<512, 0>,
                         cudaFuncAttributeMaxDynamicSharedMemorySize, SM_TOTAL_G);
    cudaFuncSetAttribute(gemm_hmma<512, 2>,
                         cudaFuncAttributeMaxDynamicSharedMemorySize, SM_TOTAL_G);
    cudaFuncSetAttribute(gemm_hmma<256, 3>,
                         cudaFuncAttributeMaxDynamicSharedMemorySize, SM_TOTAL_G3);

    // 1. prep: zero accumulators + convert all weights -> fp16 transposed
    prep_kernel<<<(PREP_CNT + 255) / 256, 256>>>(W1, W2, W3);

    // 2. split features -> fp16 hi/lo (per-vertex)
    split_rows_kernel<<<N_VERTS, 128>>>(features, p_f_hi, p_f_lo);

    // 3. G = features @ W1  (M = N_VERTS, raw f32 out)
    {
        dim3 blk(256);
        dim3 gG(4, (N_VERTS + 127) / 128);
        gemm_hmma<512, 2><<<gG, blk, SM_TOTAL_G>>>(p_f_hi, p_f_lo, p_w1t,
                                                   nullptr, p_G, nullptr, N_VERTS,
                                                   nullptr, nullptr);
    }

    // 4. h1 = relu(mean(G rows) + b1) -> fp16 split (per-face)
    gather_relu_split_kernel<<<N_FACES, 128>>>(p_G, faces, b1, p_x_hi, p_x_lo);

    // 5. layer 2; layer 3 fused with W4 head -> partial out12
    {
        dim3 blk(256);
        dim3 g12(4, (N_FACES + 127) / 128);
        gemm_hmma<512, 0><<<g12, blk, SM_TOTAL_G>>>(p_x_hi, p_x_lo, p_w2t,
                                                    b2, p_y_hi, p_y_lo, N_FACES,
                                                    nullptr, nullptr);
        dim3 g3(2, (N_FACES + 127) / 128);
        gemm_hmma<256, 3><<<g3, blk, SM_TOTAL_G3>>>(p_y_hi, p_y_lo, p_w3t,
                                                    b3, nullptr, nullptr, N_FACES,
                                                    W4, p_p12);
    }

    // 6. procrustes (combines p12 halves + b4 inline) + transform + scatter
    procrustes_kernel<<<(N_FACES + 255) / 256, 256>>>(p_p12, b4, verts, faces,
                                                      out_trans, out_rot);

    // 7. segment mean
    finalize_kernel<<<(N_VERTS + 255) / 256, 256>>>(out_vfeat);
}